// round 3
// baseline (speedup 1.0000x reference)
#include <cuda_runtime.h>
#include <cuda_bf16.h>
#include <math.h>

typedef __nv_bfloat16 bf16;
#define BATCHN 65536
#define QD 256

__device__ float g_h32 [(long)BATCHN*768];
__device__ float g_tmp32[(long)BATCHN*QD];
__device__ float g_c232 [(long)BATCHN*QD];
__device__ float g_nl32 [(long)BATCHN*QD];
__device__ float g_cur32[(long)BATCHN*QD];
__device__ bf16  g_curh[(long)BATCHN*QD],  g_curl[(long)BATCHN*QD];
__device__ bf16  g_hh  [(long)BATCHN*768], g_hl  [(long)BATCHN*768];
__device__ bf16  g_tmph[(long)BATCHN*QD],  g_tmpl[(long)BATCHN*QD];
__device__ bf16  g_c2h [(long)BATCHN*QD],  g_c2l [(long)BATCHN*QD];
__device__ bf16  g_w_h[3145728], g_w_l[3145728];
__device__ float g_wf[2*256*256];
__device__ float g_battn[2*256];
__device__ float g_lin[8*256];

__device__ __forceinline__ void split2(float v, bf16& h, bf16& l){
    h = __float2bfloat16(v);
    l = __float2bfloat16(v - __bfloat162float(h));
}
__device__ __forceinline__ unsigned cvsm(const void* p){
    return (unsigned)__cvta_generic_to_shared(p);
}
__device__ __forceinline__ void ldm4(unsigned a, unsigned& r0, unsigned& r1, unsigned& r2, unsigned& r3){
    asm volatile("ldmatrix.sync.aligned.m8n8.x4.shared.b16 {%0,%1,%2,%3}, [%4];"
                 : "=r"(r0),"=r"(r1),"=r"(r2),"=r"(r3) : "r"(a));
}
__device__ __forceinline__ void mmabf(float* c, const unsigned* a, const unsigned* b){
    asm volatile("mma.sync.aligned.m16n8k16.row.col.f32.bf16.bf16.f32 "
                 "{%0,%1,%2,%3},{%4,%5,%6,%7},{%8,%9},{%0,%1,%2,%3};"
                 : "+f"(c[0]),"+f"(c[1]),"+f"(c[2]),"+f"(c[3])
                 : "r"(a[0]),"r"(a[1]),"r"(a[2]),"r"(a[3]),"r"(b[0]),"r"(b[1]));
}
__device__ __forceinline__ void cpasync16(unsigned s, const void* g){
    asm volatile("cp.async.cg.shared.global [%0], [%1], 16;" :: "r"(s), "l"(g));
}

#define BM 128
#define BN 128
#define BKK 32
#define LDT 40                    // bf16 units; row stride 80B (16B-aligned, ldmatrix conflict-free)
#define ARR_BYTES (BM*LDT*2)      // 10240
#define OFF_AH 0
#define OFF_AL (ARR_BYTES)
#define OFF_BH (2*ARR_BYTES)
#define OFF_BL (3*ARR_BYTES)
#define STG_BYTES (4*ARR_BYTES)   // 40960
#define STAGES 4
#define SMEM_TOTAL (STAGES*STG_BYTES)  // 163840

__device__ __forceinline__ void load_stage(char* sbase,
    const bf16* Ah,const bf16* Al,const bf16* Bh,const bf16* Bl,
    long rowBase, int colBase, int K, int k0, int tid)
{
    int r0=tid>>2, kc0=(tid&3)<<3;
#pragma unroll
    for(int it=0;it<2;it++){
        int r=r0+it*64;
        long ga=(rowBase+r)*(long)K + k0 + kc0;
        long gb=((long)(colBase+r))*(long)K + k0 + kc0;
        unsigned so=cvsm(sbase + r*80 + kc0*2);
        cpasync16(so+OFF_AH, Ah+ga);
        cpasync16(so+OFF_AL, Al+ga);
        cpasync16(so+OFF_BH, Bh+gb);
        cpasync16(so+OFF_BL, Bl+gb);
    }
}

// C[M,N] = epi(A@W + bias). A hi/lo [M][K]; W transposed hi/lo [N][K].
// EPI: 0 none, 1 silu, 2 tanh, 3 fused-combine (C=ent result; reads tmpP/gpP/linP).
template<int EPI>
__global__ void __launch_bounds__(256,1) gemm_k(
    const bf16* __restrict__ Ah, const bf16* __restrict__ Al,
    const bf16* __restrict__ Bh, const bf16* __restrict__ Bl,
    const float* __restrict__ bias,
    float* __restrict__ C32, bf16* __restrict__ Ch, bf16* __restrict__ Cl,
    const float* __restrict__ tmpP, const float* __restrict__ gpP, const float* __restrict__ linP,
    int K, int N)
{
    extern __shared__ char smem[];
    const int tid=threadIdx.x, lane=tid&31, warp=tid>>5;
    const int wm=warp>>2, wn=warp&3;
    const long rowBase=(long)blockIdx.y*BM;
    const int  colBase=blockIdx.x*BN;

    float acc[4][4][4];
#pragma unroll
    for(int a=0;a<4;a++)
#pragma unroll
    for(int b=0;b<4;b++)
#pragma unroll
    for(int c=0;c<4;c++) acc[a][b][c]=0.f;

    const int nIter=K/BKK;
    // preload 3 stages
#pragma unroll
    for(int s=0;s<STAGES-1;s++){
        if(s<nIter) load_stage(smem+s*STG_BYTES, Ah,Al,Bh,Bl, rowBase,colBase, K, s*BKK, tid);
        asm volatile("cp.async.commit_group;" ::: "memory");
    }

    for(int i=0;i<nIter;i++){
        asm volatile("cp.async.wait_group %0;" :: "n"(STAGES-2) : "memory");
        __syncthreads();
        int pf=i+STAGES-1;
        if(pf<nIter) load_stage(smem+(pf&(STAGES-1))*STG_BYTES, Ah,Al,Bh,Bl, rowBase,colBase, K, pf*BKK, tid);
        asm volatile("cp.async.commit_group;" ::: "memory");

        char* sb = smem + (i&(STAGES-1))*STG_BYTES;
        bf16* sAh=(bf16*)(sb+OFF_AH); bf16* sAl=(bf16*)(sb+OFF_AL);
        bf16* sBh=(bf16*)(sb+OFF_BH); bf16* sBl=(bf16*)(sb+OFF_BL);
#pragma unroll
        for(int ks=0;ks<2;ks++){
            unsigned aH[4][4], aL[4][4], bH[4][2], bL[4][2];
            const int colo = ks*16 + ((lane>>4)<<3);
#pragma unroll
            for(int mt=0;mt<4;mt++){
                int row=wm*64+mt*16+(lane&15);
                ldm4(cvsm(sAh+row*LDT+colo), aH[mt][0],aH[mt][1],aH[mt][2],aH[mt][3]);
                ldm4(cvsm(sAl+row*LDT+colo), aL[mt][0],aL[mt][1],aL[mt][2],aL[mt][3]);
            }
#pragma unroll
            for(int np=0;np<2;np++){
                int row=wn*32+np*16+(lane&15);
                unsigned t0,t1,t2,t3;
                ldm4(cvsm(sBh+row*LDT+colo), t0,t1,t2,t3);
                bH[2*np][0]=t0; bH[2*np][1]=t2; bH[2*np+1][0]=t1; bH[2*np+1][1]=t3;
                ldm4(cvsm(sBl+row*LDT+colo), t0,t1,t2,t3);
                bL[2*np][0]=t0; bL[2*np][1]=t2; bL[2*np+1][0]=t1; bL[2*np+1][1]=t3;
            }
#pragma unroll
            for(int mt=0;mt<4;mt++)
#pragma unroll
            for(int nt=0;nt<4;nt++){
                mmabf(acc[mt][nt], aH[mt], bH[nt]);
                mmabf(acc[mt][nt], aH[mt], bL[nt]);
                mmabf(acc[mt][nt], aL[mt], bH[nt]);
            }
        }
        __syncthreads();
    }

#pragma unroll
    for(int mt=0;mt<4;mt++)
#pragma unroll
    for(int nt=0;nt<4;nt++){
        int n0=colBase+wn*32+nt*8+((lane&3)<<1);
        float b0=0.f,b1=0.f;
        if(EPI!=3 && bias){ b0=bias[n0]; b1=bias[n0+1]; }
        float l0=0,p30=0,p40=0,p50=0,l1=0,p31=0,p41=0,p51=0;
        if(EPI==3){
            l0=linP[n0]; p30=gpP[n0*6+3]; p40=gpP[n0*6+4]; p50=gpP[n0*6+5];
            l1=linP[n0+1]; p31=gpP[(n0+1)*6+3]; p41=gpP[(n0+1)*6+4]; p51=gpP[(n0+1)*6+5];
        }
#pragma unroll
        for(int hh=0;hh<2;hh++){
            long row=rowBase+wm*64+mt*16+(lane>>2)+hh*8;
            long o=row*(long)N+n0;
            float v0=acc[mt][nt][2*hh]+b0, v1=acc[mt][nt][2*hh+1]+b1;
            if(EPI==1){ v0*=1.f/(1.f+__expf(-v0)); v1*=1.f/(1.f+__expf(-v1)); }
            if(EPI==2){ v0=tanhf(v0); v1=tanhf(v1); }
            if(EPI==3){
                float t0v=tmpP[o], t1v=tmpP[o+1];
                float g0=(l0*t0v + 0.5f*sinf(p30*t0v+p40) + 0.5f*cosf(p50*t0v))*0.25f;
                float g1=(l1*t1v + 0.5f*sinf(p31*t1v+p41) + 0.5f*cosf(p51*t1v))*0.25f;
                v0=(t0v + 0.3f*g0 + 0.2f*v0)*(1.0f/1.5f);
                v1=(t1v + 0.3f*g1 + 0.2f*v1)*(1.0f/1.5f);
            }
            if(C32){ float2 f; f.x=v0; f.y=v1; *(float2*)(C32+o)=f; }
            if(Ch){
                bf16 h0,q0,h1,q1; split2(v0,h0,q0); split2(v1,h1,q1);
                __nv_bfloat162 ph,pl; ph.x=h0; ph.y=h1; pl.x=q0; pl.y=q1;
                *(__nv_bfloat162*)(Ch+o)=ph; *(__nv_bfloat162*)(Cl+o)=pl;
            }
        }
    }
}

__global__ void k_init(const float* __restrict__ x, float* __restrict__ cur,
                       bf16* __restrict__ ch, bf16* __restrict__ cl){
    long idx=(long)blockIdx.x*256+threadIdx.x;
    float v=x[idx]; cur[idx]=v;
    bf16 h,l; split2(v,h,l); ch[idx]=h; cl[idx]=l;
}

// blockIdx.y = segment index; W/oh/ol advance by seg per segment.
__global__ void k_split_t(const float* __restrict__ W, bf16* __restrict__ oh, bf16* __restrict__ ol,
                          int K, int N, int do_tanh, long seg){
    long base=(long)blockIdx.y*seg;
    long idx=(long)blockIdx.x*256+threadIdx.x;
    if(idx>=seg) return;
    int k=(int)(idx/N), n=(int)(idx%N);
    float v=W[base+idx]; if(do_tanh) v=tanhf(v);
    bf16 h,l; split2(v,h,l);
    oh[base+(long)n*K+k]=h; ol[base+(long)n*K+k]=l;
}

__global__ void k_attn_fuse(const float* __restrict__ wqkv, const float* __restrict__ bqkv,
                            const float* __restrict__ wo, const float* __restrict__ bo,
                            float* __restrict__ wf, float* __restrict__ battn){
    int i=blockIdx.y;
    int idx=blockIdx.x*256+threadIdx.x;
    int k=idx>>8, n=idx&255;
    const float* Wv=wqkv+(long)i*256*768+512;
    const float* Wo=wo+(long)i*256*256;
    float s=0.f;
    for(int j=0;j<256;j++) s+=Wv[(long)k*768+j]*Wo[(long)j*256+n];
    wf[(long)i*65536+idx]=s;
    if(k==0){
        float sb=bo[i*256+n];
        for(int j=0;j<256;j++) sb+=bqkv[(long)i*768+512+j]*Wo[(long)j*256+n];
        battn[i*256+n]=sb;
    }
}

__global__ void k_lin(const float* __restrict__ gp, float* __restrict__ lin){
    int idx=blockIdx.x*256+threadIdx.x;
    const float* p=gp+(long)idx*6;
    lin[idx]=sinf(p[0])+cosf(p[1])+tanhf(p[2]);
}

__global__ void k_ln_gelu(const float* __restrict__ h, const float* __restrict__ w, const float* __restrict__ b,
                          bf16* __restrict__ oh, bf16* __restrict__ ol){
    int row=blockIdx.x*8+(threadIdx.x>>5);
    int lane=threadIdx.x&31;
    const float* hr=h+(long)row*768;
    float v[24]; float s=0.f,s2=0.f;
#pragma unroll
    for(int j=0;j<24;j++){ float x=hr[lane+32*j]; v[j]=x; s+=x; s2+=x*x; }
#pragma unroll
    for(int o=16;o;o>>=1){ s+=__shfl_xor_sync(0xffffffffu,s,o); s2+=__shfl_xor_sync(0xffffffffu,s2,o); }
    float mu=s*(1.f/768.f);
    float var=s2*(1.f/768.f)-mu*mu;
    float inv=rsqrtf(var+1e-5f);
    long base=(long)row*768;
#pragma unroll
    for(int j=0;j<24;j++){
        int q=lane+32*j;
        float y=(v[j]-mu)*inv*w[q]+b[q];
        float g=0.5f*y*(1.f+erff(y*0.70710678118654752f));
        bf16 hh,ll; split2(g,hh,ll);
        oh[base+q]=hh; ol[base+q]=ll;
    }
}

__global__ void k_final(const float* __restrict__ c2, const float* __restrict__ nl,
                        float* __restrict__ cur, bf16* __restrict__ ch, bf16* __restrict__ cl,
                        float* __restrict__ outp, float alpha){
    int row=blockIdx.x*8+(threadIdx.x>>5);
    int lane=threadIdx.x&31;
    long base=(long)row*QD;
    float v[8]; float ss=0.f;
#pragma unroll
    for(int j=0;j<8;j++){
        int q=lane+32*j;
        float x=c2[base+q];
        if(nl) x+=0.1f*nl[base+q];
        float y=alpha*x+(1.f-alpha)*cur[base+q];
        v[j]=y; ss+=y*y;
    }
#pragma unroll
    for(int o=16;o;o>>=1) ss+=__shfl_xor_sync(0xffffffffu,ss,o);
    float inv=1.f/(sqrtf(ss)+1e-8f);
#pragma unroll
    for(int j=0;j<8;j++){
        int q=lane+32*j;
        float y=tanhf(v[j]*inv);
        if(outp) outp[base+q]=y;
        else{ cur[base+q]=y; bf16 h,l; split2(y,h,l); ch[base+q]=h; cl[base+q]=l; }
    }
}

static void* symaddr(const void* s){ void* p=nullptr; cudaGetSymbolAddress(&p, s); return p; }

static void gemm(int epi, const bf16* Ah,const bf16* Al,const bf16* Bh,const bf16* Bl,
                 const float* bias, float* C32, bf16* Ch, bf16* Cl,
                 const float* tmpP, const float* gpP, const float* linP, int K,int N){
    dim3 grid(N/128, BATCHN/128);
    if(epi==0)      gemm_k<0><<<grid,256,SMEM_TOTAL>>>(Ah,Al,Bh,Bl,bias,C32,Ch,Cl,tmpP,gpP,linP,K,N);
    else if(epi==1) gemm_k<1><<<grid,256,SMEM_TOTAL>>>(Ah,Al,Bh,Bl,bias,C32,Ch,Cl,tmpP,gpP,linP,K,N);
    else if(epi==2) gemm_k<2><<<grid,256,SMEM_TOTAL>>>(Ah,Al,Bh,Bl,bias,C32,Ch,Cl,tmpP,gpP,linP,K,N);
    else            gemm_k<3><<<grid,256,SMEM_TOTAL>>>(Ah,Al,Bh,Bl,bias,C32,Ch,Cl,tmpP,gpP,linP,K,N);
}

extern "C" void kernel_launch(void* const* d_in, const int* in_sizes, int n_in,
                              void* d_out, int out_size){
    (void)in_sizes;(void)n_in;(void)out_size;
    cudaFuncSetAttribute(gemm_k<0>, cudaFuncAttributeMaxDynamicSharedMemorySize, SMEM_TOTAL);
    cudaFuncSetAttribute(gemm_k<1>, cudaFuncAttributeMaxDynamicSharedMemorySize, SMEM_TOTAL);
    cudaFuncSetAttribute(gemm_k<2>, cudaFuncAttributeMaxDynamicSharedMemorySize, SMEM_TOTAL);
    cudaFuncSetAttribute(gemm_k<3>, cudaFuncAttributeMaxDynamicSharedMemorySize, SMEM_TOTAL);

    const float* x   =(const float*)d_in[0];
    const float* d0w1=(const float*)d_in[1];
    const float* d0b1=(const float*)d_in[2];
    const float* lnw =(const float*)d_in[3];
    const float* lnb =(const float*)d_in[4];
    const float* d0w2=(const float*)d_in[5];
    const float* d0b2=(const float*)d_in[6];
    const float* d1w1=(const float*)d_in[7];
    const float* d1b1=(const float*)d_in[8];
    const float* d1w2=(const float*)d_in[9];
    const float* d1b2=(const float*)d_in[10];
    const float* wqkv=(const float*)d_in[11];
    const float* bqkv=(const float*)d_in[12];
    const float* wo  =(const float*)d_in[13];
    const float* bo  =(const float*)d_in[14];
    const float* gp  =(const float*)d_in[15];
    const float* ent =(const float*)d_in[16];
    const float* nw1 =(const float*)d_in[17];
    const float* nb1 =(const float*)d_in[18];
    const float* nw2 =(const float*)d_in[19];
    const float* nb2 =(const float*)d_in[20];

    float* h32  =(float*)symaddr(g_h32);
    float* tmp32=(float*)symaddr(g_tmp32);
    float* c232 =(float*)symaddr(g_c232);
    float* nl32 =(float*)symaddr(g_nl32);
    float* cur32=(float*)symaddr(g_cur32);
    bf16* curh=(bf16*)symaddr(g_curh); bf16* curl=(bf16*)symaddr(g_curl);
    bf16* hh_ =(bf16*)symaddr(g_hh);   bf16* hl_ =(bf16*)symaddr(g_hl);
    bf16* tmph=(bf16*)symaddr(g_tmph); bf16* tmpl=(bf16*)symaddr(g_tmpl);
    bf16* c2h =(bf16*)symaddr(g_c2h);  bf16* c2l =(bf16*)symaddr(g_c2l);
    bf16* wh  =(bf16*)symaddr(g_w_h);  bf16* wl  =(bf16*)symaddr(g_w_l);
    float* wf   =(float*)symaddr(g_wf);
    float* battn=(float*)symaddr(g_battn);
    float* lin  =(float*)symaddr(g_lin);

    const long O_D0W1=0, O_D0W2=589824, O_D1W1=1179648, O_D1W2=1572864;
    const long O_ATT=1966080, O_TENT=2097152, O_NW1=2621440, O_NW2=2883584;

    // prep (batched over blockIdx.y)
    k_split_t<<<dim3(768,3),256>>>(d0w1, wh+O_D0W1, wl+O_D0W1, 256,768,0,196608);
    k_split_t<<<dim3(768,3),256>>>(d0w2, wh+O_D0W2, wl+O_D0W2, 768,256,0,196608);
    k_split_t<<<dim3(512,3),256>>>(d1w1, wh+O_D1W1, wl+O_D1W1, 256,512,0,131072);
    k_split_t<<<dim3(512,3),256>>>(d1w2, wh+O_D1W2, wl+O_D1W2, 512,256,0,131072);
    k_attn_fuse<<<dim3(256,2),256>>>(wqkv,bqkv,wo,bo,wf,battn);
    k_split_t<<<dim3(256,2),256>>>(wf,  wh+O_ATT,  wl+O_ATT,  256,256,0,65536);
    k_split_t<<<dim3(256,8),256>>>(ent, wh+O_TENT, wl+O_TENT, 256,256,1,65536);
    k_split_t<<<dim3(256,4),256>>>(nw1, wh+O_NW1,  wl+O_NW1,  256,256,0,65536);
    k_split_t<<<dim3(256,4),256>>>(nw2, wh+O_NW2,  wl+O_NW2,  256,256,0,65536);
    k_lin<<<8,256>>>(gp, lin);
    k_init<<<BATCHN*QD/256,256>>>(x, cur32, curh, curl);

    for(int li=0;li<8;li++){
        int t=li%3;
        if(t==0){
            int i=li/3;
            gemm(0, curh,curl, wh+O_D0W1+(long)i*196608, wl+O_D0W1+(long)i*196608,
                 d0b1+(long)i*768, h32, nullptr,nullptr, nullptr,nullptr,nullptr, 256,768);
            k_ln_gelu<<<BATCHN/8,256>>>(h32, lnw+(long)i*768, lnb+(long)i*768, hh_, hl_);
            gemm(0, hh_,hl_, wh+O_D0W2+(long)i*196608, wl+O_D0W2+(long)i*196608,
                 d0b2+(long)i*256, tmp32, tmph,tmpl, nullptr,nullptr,nullptr, 768,256);
        } else if(t==1){
            int i=(li-1)/3;
            gemm(1, curh,curl, wh+O_D1W1+(long)i*131072, wl+O_D1W1+(long)i*131072,
                 d1b1+(long)i*512, nullptr, hh_,hl_, nullptr,nullptr,nullptr, 256,512);
            gemm(0, hh_,hl_, wh+O_D1W2+(long)i*131072, wl+O_D1W2+(long)i*131072,
                 d1b2+(long)i*256, tmp32, tmph,tmpl, nullptr,nullptr,nullptr, 512,256);
        } else {
            int i=(li-2)/3;
            gemm(0, curh,curl, wh+O_ATT+(long)i*65536, wl+O_ATT+(long)i*65536,
                 battn+(long)i*256, tmp32, tmph,tmpl, nullptr,nullptr,nullptr, 256,256);
        }
        // entangle GEMM with fused gate/combine epilogue -> c2
        gemm(3, tmph,tmpl, wh+O_TENT+(long)li*65536, wl+O_TENT+(long)li*65536,
             nullptr, c232, c2h,c2l, tmp32, gp+(long)li*256*6, lin+(long)li*256, 256,256);

        const float* nlptr=nullptr;
        if(li&1){
            int j=li/2;
            gemm(2, c2h,c2l, wh+O_NW1+(long)j*65536, wl+O_NW1+(long)j*65536,
                 nb1+(long)j*256, nullptr, hh_,hl_, nullptr,nullptr,nullptr, 256,256);
            gemm(0, hh_,hl_, wh+O_NW2+(long)j*65536, wl+O_NW2+(long)j*65536,
                 nb2+(long)j*256, nl32, nullptr,nullptr, nullptr,nullptr,nullptr, 256,256);
            nlptr=nl32;
        }
        float alpha=(li<4)?0.8f:0.6f;
        float* outp=(li==7)?(float*)d_out:nullptr;
        k_final<<<BATCHN/8,256>>>(c232, nlptr, cur32, curh, curl, outp, alpha);
    }
}

// round 4
// speedup vs baseline: 1.5193x; 1.5193x over previous
#include <cuda_runtime.h>
#include <cuda_bf16.h>
#include <math.h>

typedef __nv_bfloat16 bf16;
#define BATCHN 65536
#define QD 256

__device__ float g_h32 [(long)BATCHN*768];
__device__ float g_nl32[(long)BATCHN*QD];
__device__ bf16  g_curh[(long)BATCHN*QD],  g_curl[(long)BATCHN*QD];
__device__ bf16  g_hh  [(long)BATCHN*768], g_hl  [(long)BATCHN*768];
__device__ bf16  g_tmph[(long)BATCHN*QD],  g_tmpl[(long)BATCHN*QD];
__device__ bf16  g_c2h [(long)BATCHN*QD],  g_c2l [(long)BATCHN*QD];
__device__ bf16  g_w_h[3145728], g_w_l[3145728];
__device__ float g_wf[2*256*256];
__device__ float g_battn[2*256];
__device__ float g_lin[8*256];

__device__ __forceinline__ void split2(float v, bf16& h, bf16& l){
    h = __float2bfloat16(v);
    l = __float2bfloat16(v - __bfloat162float(h));
}
__device__ __forceinline__ unsigned cvsm(const void* p){
    return (unsigned)__cvta_generic_to_shared(p);
}
__device__ __forceinline__ void ldm4(unsigned a, unsigned& r0, unsigned& r1, unsigned& r2, unsigned& r3){
    asm volatile("ldmatrix.sync.aligned.m8n8.x4.shared.b16 {%0,%1,%2,%3}, [%4];"
                 : "=r"(r0),"=r"(r1),"=r"(r2),"=r"(r3) : "r"(a));
}
__device__ __forceinline__ void mmabf(float* c, const unsigned* a, const unsigned* b){
    asm volatile("mma.sync.aligned.m16n8k16.row.col.f32.bf16.bf16.f32 "
                 "{%0,%1,%2,%3},{%4,%5,%6,%7},{%8,%9},{%0,%1,%2,%3};"
                 : "+f"(c[0]),"+f"(c[1]),"+f"(c[2]),"+f"(c[3])
                 : "r"(a[0]),"r"(a[1]),"r"(a[2]),"r"(a[3]),"r"(b[0]),"r"(b[1]));
}

#define BM 128
#define BN 128
#define BKK 32
#define LDT 40   // bf16 units; 80B rows, ldmatrix conflict-free

// C[M,N] = epi(A@W + bias). A hi/lo [M][K]; W transposed hi/lo [N][K].
// EPI: 0 none, 1 silu, 2 tanh, 3 fused-combine (reads tmph/tmpl, gpP, linP).
template<int EPI>
__global__ void __launch_bounds__(256,1) gemm_k(
    const bf16* __restrict__ Ah, const bf16* __restrict__ Al,
    const bf16* __restrict__ Bh, const bf16* __restrict__ Bl,
    const float* __restrict__ bias,
    float* __restrict__ C32, bf16* __restrict__ Ch, bf16* __restrict__ Cl,
    const bf16* __restrict__ tmphP, const bf16* __restrict__ tmplP,
    const float* __restrict__ gpP, const float* __restrict__ linP,
    int K, int N)
{
    __shared__ bf16 sAh[BM*LDT], sAl[BM*LDT], sBh[BN*LDT], sBl[BN*LDT];
    const int tid=threadIdx.x, lane=tid&31, warp=tid>>5;
    const int wm=warp>>2, wn=warp&3;
    const long rowBase=(long)blockIdx.y*BM;
    const int  colBase=blockIdx.x*BN;

    float acc[4][4][4];
#pragma unroll
    for(int a=0;a<4;a++)
#pragma unroll
    for(int b=0;b<4;b++)
#pragma unroll
    for(int c=0;c<4;c++) acc[a][b][c]=0.f;

    const int r0=tid>>2, kc0=(tid&3)<<3;
    const int nIter=K/BKK;

    uint4 pAh[2],pAl[2],pBh[2],pBl[2];
    // prologue: fetch k0=0 into regs
#pragma unroll
    for(int it=0;it<2;it++){
        int r=r0+it*64;
        long ga=(rowBase+r)*(long)K + kc0;
        long gb=((long)(colBase+r))*(long)K + kc0;
        pAh[it]=*(const uint4*)(Ah+ga); pAl[it]=*(const uint4*)(Al+ga);
        pBh[it]=*(const uint4*)(Bh+gb); pBl[it]=*(const uint4*)(Bl+gb);
    }

    for(int i=0;i<nIter;i++){
        // store prefetched regs to smem
#pragma unroll
        for(int it=0;it<2;it++){
            int so=(r0+it*64)*LDT+kc0;
            *(uint4*)(sAh+so)=pAh[it]; *(uint4*)(sAl+so)=pAl[it];
            *(uint4*)(sBh+so)=pBh[it]; *(uint4*)(sBl+so)=pBl[it];
        }
        __syncthreads();
        // issue next tile's loads; latency overlaps with compute below
        if(i+1<nIter){
            int k0=(i+1)*BKK;
#pragma unroll
            for(int it=0;it<2;it++){
                int r=r0+it*64;
                long ga=(rowBase+r)*(long)K + k0 + kc0;
                long gb=((long)(colBase+r))*(long)K + k0 + kc0;
                pAh[it]=*(const uint4*)(Ah+ga); pAl[it]=*(const uint4*)(Al+ga);
                pBh[it]=*(const uint4*)(Bh+gb); pBl[it]=*(const uint4*)(Bl+gb);
            }
        }
#pragma unroll
        for(int ks=0;ks<2;ks++){
            unsigned aH[4][4], aL[4][4], bH[4][2], bL[4][2];
            const int colo = ks*16 + ((lane>>4)<<3);
#pragma unroll
            for(int mt=0;mt<4;mt++){
                int row=wm*64+mt*16+(lane&15);
                ldm4(cvsm(sAh+row*LDT+colo), aH[mt][0],aH[mt][1],aH[mt][2],aH[mt][3]);
                ldm4(cvsm(sAl+row*LDT+colo), aL[mt][0],aL[mt][1],aL[mt][2],aL[mt][3]);
            }
#pragma unroll
            for(int np=0;np<2;np++){
                int row=wn*32+np*16+(lane&15);
                unsigned t0,t1,t2,t3;
                ldm4(cvsm(sBh+row*LDT+colo), t0,t1,t2,t3);
                bH[2*np][0]=t0; bH[2*np][1]=t2; bH[2*np+1][0]=t1; bH[2*np+1][1]=t3;
                ldm4(cvsm(sBl+row*LDT+colo), t0,t1,t2,t3);
                bL[2*np][0]=t0; bL[2*np][1]=t2; bL[2*np+1][0]=t1; bL[2*np+1][1]=t3;
            }
#pragma unroll
            for(int mt=0;mt<4;mt++)
#pragma unroll
            for(int nt=0;nt<4;nt++){
                mmabf(acc[mt][nt], aH[mt], bH[nt]);
                mmabf(acc[mt][nt], aH[mt], bL[nt]);
                mmabf(acc[mt][nt], aL[mt], bH[nt]);
            }
        }
        __syncthreads();
    }

#pragma unroll
    for(int mt=0;mt<4;mt++)
#pragma unroll
    for(int nt=0;nt<4;nt++){
        int n0=colBase+wn*32+nt*8+((lane&3)<<1);
        float b0=0.f,b1=0.f;
        if(EPI!=3 && bias){ b0=bias[n0]; b1=bias[n0+1]; }
        float l0=0,p30=0,p40=0,p50=0,l1=0,p31=0,p41=0,p51=0;
        if(EPI==3){
            l0=linP[n0]; p30=gpP[n0*6+3]; p40=gpP[n0*6+4]; p50=gpP[n0*6+5];
            l1=linP[n0+1]; p31=gpP[(n0+1)*6+3]; p41=gpP[(n0+1)*6+4]; p51=gpP[(n0+1)*6+5];
        }
#pragma unroll
        for(int hh=0;hh<2;hh++){
            long row=rowBase+wm*64+mt*16+(lane>>2)+hh*8;
            long o=row*(long)N+n0;
            float v0=acc[mt][nt][2*hh]+b0, v1=acc[mt][nt][2*hh+1]+b1;
            if(EPI==1){ v0*=1.f/(1.f+__expf(-v0)); v1*=1.f/(1.f+__expf(-v1)); }
            if(EPI==2){ v0=tanhf(v0); v1=tanhf(v1); }
            if(EPI==3){
                __nv_bfloat162 th=*(const __nv_bfloat162*)(tmphP+o);
                __nv_bfloat162 tl=*(const __nv_bfloat162*)(tmplP+o);
                float t0v=__bfloat162float(th.x)+__bfloat162float(tl.x);
                float t1v=__bfloat162float(th.y)+__bfloat162float(tl.y);
                float g0=(l0*t0v + 0.5f*sinf(p30*t0v+p40) + 0.5f*cosf(p50*t0v))*0.25f;
                float g1=(l1*t1v + 0.5f*sinf(p31*t1v+p41) + 0.5f*cosf(p51*t1v))*0.25f;
                v0=(t0v + 0.3f*g0 + 0.2f*v0)*(1.0f/1.5f);
                v1=(t1v + 0.3f*g1 + 0.2f*v1)*(1.0f/1.5f);
            }
            if(C32){ float2 f; f.x=v0; f.y=v1; *(float2*)(C32+o)=f; }
            if(Ch){
                bf16 h0,q0,h1,q1; split2(v0,h0,q0); split2(v1,h1,q1);
                __nv_bfloat162 ph,pl; ph.x=h0; ph.y=h1; pl.x=q0; pl.y=q1;
                *(__nv_bfloat162*)(Ch+o)=ph; *(__nv_bfloat162*)(Cl+o)=pl;
            }
        }
    }
}

__global__ void k_init(const float* __restrict__ x,
                       bf16* __restrict__ ch, bf16* __restrict__ cl){
    long idx=(long)blockIdx.x*256+threadIdx.x;
    float v=x[idx];
    bf16 h,l; split2(v,h,l); ch[idx]=h; cl[idx]=l;
}

__device__ __forceinline__ void split_store(const float* W, bf16* oh, bf16* ol,
                                            int K, int N, int do_tanh, long seg, long idx){
    if(idx>=seg) return;
    int k=(int)(idx/N), n=(int)(idx%N);
    float v=W[idx]; if(do_tanh) v=tanhf(v);
    bf16 h,l; split2(v,h,l);
    oh[(long)n*K+k]=h; ol[(long)n*K+k]=l;
}

// big weights: y 0..11 -> d0w1[0..2], d0w2[0..2], d1w1[0..2], d1w2[0..2]
__global__ void k_split_big(const float* __restrict__ d0w1, const float* __restrict__ d0w2,
                            const float* __restrict__ d1w1, const float* __restrict__ d1w2,
                            bf16* __restrict__ wh, bf16* __restrict__ wl){
    const long O_D0W1=0, O_D0W2=589824, O_D1W1=1179648, O_D1W2=1572864;
    long idx=(long)blockIdx.x*256+threadIdx.x;
    int y=blockIdx.y;
    if(y<3){        long b=(long)y*196608;
        split_store(d0w1+b, wh+O_D0W1+b, wl+O_D0W1+b, 256,768,0,196608,idx);
    } else if(y<6){ long b=(long)(y-3)*196608;
        split_store(d0w2+b, wh+O_D0W2+b, wl+O_D0W2+b, 768,256,0,196608,idx);
    } else if(y<9){ long b=(long)(y-6)*131072;
        split_store(d1w1+b, wh+O_D1W1+b, wl+O_D1W1+b, 256,512,0,131072,idx);
    } else {        long b=(long)(y-9)*131072;
        split_store(d1w2+b, wh+O_D1W2+b, wl+O_D1W2+b, 512,256,0,131072,idx);
    }
}

// small 256x256 weights: y 0..17 -> wf[0..1], ent[0..7] (tanh), nw1[0..3], nw2[0..3]
__global__ void k_split_small(const float* __restrict__ wf, const float* __restrict__ ent,
                              const float* __restrict__ nw1, const float* __restrict__ nw2,
                              bf16* __restrict__ wh, bf16* __restrict__ wl){
    const long O_ATT=1966080, O_TENT=2097152, O_NW1=2621440, O_NW2=2883584;
    long idx=(long)blockIdx.x*256+threadIdx.x;
    int y=blockIdx.y;
    if(y<2){         long b=(long)y*65536;
        split_store(wf+b,  wh+O_ATT+b,  wl+O_ATT+b,  256,256,0,65536,idx);
    } else if(y<10){ long b=(long)(y-2)*65536;
        split_store(ent+b, wh+O_TENT+b, wl+O_TENT+b, 256,256,1,65536,idx);
    } else if(y<14){ long b=(long)(y-10)*65536;
        split_store(nw1+b, wh+O_NW1+b,  wl+O_NW1+b,  256,256,0,65536,idx);
    } else {         long b=(long)(y-14)*65536;
        split_store(nw2+b, wh+O_NW2+b,  wl+O_NW2+b,  256,256,0,65536,idx);
    }
}

__global__ void k_attn_fuse(const float* __restrict__ wqkv, const float* __restrict__ bqkv,
                            const float* __restrict__ wo, const float* __restrict__ bo,
                            float* __restrict__ wf, float* __restrict__ battn){
    int i=blockIdx.y;
    int idx=blockIdx.x*256+threadIdx.x;
    int k=idx>>8, n=idx&255;
    const float* Wv=wqkv+(long)i*256*768+512;
    const float* Wo=wo+(long)i*256*256;
    float s=0.f;
    for(int j=0;j<256;j++) s+=Wv[(long)k*768+j]*Wo[(long)j*256+n];
    wf[(long)i*65536+idx]=s;
    if(k==0){
        float sb=bo[i*256+n];
        for(int j=0;j<256;j++) sb+=bqkv[(long)i*768+512+j]*Wo[(long)j*256+n];
        battn[i*256+n]=sb;
    }
}

__global__ void k_lin(const float* __restrict__ gp, float* __restrict__ lin){
    int idx=blockIdx.x*256+threadIdx.x;
    const float* p=gp+(long)idx*6;
    lin[idx]=sinf(p[0])+cosf(p[1])+tanhf(p[2]);
}

__global__ void k_ln_gelu(const float* __restrict__ h, const float* __restrict__ w, const float* __restrict__ b,
                          bf16* __restrict__ oh, bf16* __restrict__ ol){
    int row=blockIdx.x*8+(threadIdx.x>>5);
    int lane=threadIdx.x&31;
    const float* hr=h+(long)row*768;
    float v[24]; float s=0.f,s2=0.f;
#pragma unroll
    for(int j=0;j<24;j++){ float x=hr[lane+32*j]; v[j]=x; s+=x; s2+=x*x; }
#pragma unroll
    for(int o=16;o;o>>=1){ s+=__shfl_xor_sync(0xffffffffu,s,o); s2+=__shfl_xor_sync(0xffffffffu,s2,o); }
    float mu=s*(1.f/768.f);
    float var=s2*(1.f/768.f)-mu*mu;
    float inv=rsqrtf(var+1e-5f);
    long base=(long)row*768;
#pragma unroll
    for(int j=0;j<24;j++){
        int q=lane+32*j;
        float y=(v[j]-mu)*inv*w[q]+b[q];
        float g=0.5f*y*(1.f+erff(y*0.70710678118654752f));
        bf16 hh,ll; split2(g,hh,ll);
        oh[base+q]=hh; ol[base+q]=ll;
    }
}

__global__ void k_final(const bf16* __restrict__ c2h, const bf16* __restrict__ c2l,
                        const float* __restrict__ nl,
                        bf16* __restrict__ ch, bf16* __restrict__ cl,
                        float* __restrict__ outp, float alpha){
    int row=blockIdx.x*8+(threadIdx.x>>5);
    int lane=threadIdx.x&31;
    long base=(long)row*QD;
    float v[8]; float ss=0.f;
#pragma unroll
    for(int j=0;j<8;j++){
        int q=lane+32*j;
        float x=__bfloat162float(c2h[base+q])+__bfloat162float(c2l[base+q]);
        if(nl) x+=0.1f*nl[base+q];
        float res=__bfloat162float(ch[base+q])+__bfloat162float(cl[base+q]);
        float y=alpha*x+(1.f-alpha)*res;
        v[j]=y; ss+=y*y;
    }
#pragma unroll
    for(int o=16;o;o>>=1) ss+=__shfl_xor_sync(0xffffffffu,ss,o);
    float inv=1.f/(sqrtf(ss)+1e-8f);
#pragma unroll
    for(int j=0;j<8;j++){
        int q=lane+32*j;
        float y=tanhf(v[j]*inv);
        if(outp) outp[base+q]=y;
        else{ bf16 h,l; split2(y,h,l); ch[base+q]=h; cl[base+q]=l; }
    }
}

static void* symaddr(const void* s){ void* p=nullptr; cudaGetSymbolAddress(&p, s); return p; }

static void gemm(int epi, const bf16* Ah,const bf16* Al,const bf16* Bh,const bf16* Bl,
                 const float* bias, float* C32, bf16* Ch, bf16* Cl,
                 const bf16* tmphP, const bf16* tmplP, const float* gpP, const float* linP,
                 int K,int N){
    dim3 grid(N/128, BATCHN/128);
    if(epi==0)      gemm_k<0><<<grid,256>>>(Ah,Al,Bh,Bl,bias,C32,Ch,Cl,tmphP,tmplP,gpP,linP,K,N);
    else if(epi==1) gemm_k<1><<<grid,256>>>(Ah,Al,Bh,Bl,bias,C32,Ch,Cl,tmphP,tmplP,gpP,linP,K,N);
    else if(epi==2) gemm_k<2><<<grid,256>>>(Ah,Al,Bh,Bl,bias,C32,Ch,Cl,tmphP,tmplP,gpP,linP,K,N);
    else            gemm_k<3><<<grid,256>>>(Ah,Al,Bh,Bl,bias,C32,Ch,Cl,tmphP,tmplP,gpP,linP,K,N);
}

extern "C" void kernel_launch(void* const* d_in, const int* in_sizes, int n_in,
                              void* d_out, int out_size){
    (void)in_sizes;(void)n_in;(void)out_size;
    const float* x   =(const float*)d_in[0];
    const float* d0w1=(const float*)d_in[1];
    const float* d0b1=(const float*)d_in[2];
    const float* lnw =(const float*)d_in[3];
    const float* lnb =(const float*)d_in[4];
    const float* d0w2=(const float*)d_in[5];
    const float* d0b2=(const float*)d_in[6];
    const float* d1w1=(const float*)d_in[7];
    const float* d1b1=(const float*)d_in[8];
    const float* d1w2=(const float*)d_in[9];
    const float* d1b2=(const float*)d_in[10];
    const float* wqkv=(const float*)d_in[11];
    const float* bqkv=(const float*)d_in[12];
    const float* wo  =(const float*)d_in[13];
    const float* bo  =(const float*)d_in[14];
    const float* gp  =(const float*)d_in[15];
    const float* ent =(const float*)d_in[16];
    const float* nw1 =(const float*)d_in[17];
    const float* nb1 =(const float*)d_in[18];
    const float* nw2 =(const float*)d_in[19];
    const float* nb2 =(const float*)d_in[20];

    float* h32  =(float*)symaddr(g_h32);
    float* nl32 =(float*)symaddr(g_nl32);
    bf16* curh=(bf16*)symaddr(g_curh); bf16* curl=(bf16*)symaddr(g_curl);
    bf16* hh_ =(bf16*)symaddr(g_hh);   bf16* hl_ =(bf16*)symaddr(g_hl);
    bf16* tmph=(bf16*)symaddr(g_tmph); bf16* tmpl=(bf16*)symaddr(g_tmpl);
    bf16* c2h =(bf16*)symaddr(g_c2h);  bf16* c2l =(bf16*)symaddr(g_c2l);
    bf16* wh  =(bf16*)symaddr(g_w_h);  bf16* wl  =(bf16*)symaddr(g_w_l);
    float* wf   =(float*)symaddr(g_wf);
    float* battn=(float*)symaddr(g_battn);
    float* lin  =(float*)symaddr(g_lin);

    const long O_D0W1=0, O_D0W2=589824, O_D1W1=1179648, O_D1W2=1572864;
    const long O_ATT=1966080, O_TENT=2097152, O_NW1=2621440, O_NW2=2883584;

    // exactly 5 prep launches so ncu (-s 5 -c 1) profiles the first GEMM
    k_attn_fuse <<<dim3(256,2),256>>>(wqkv,bqkv,wo,bo,wf,battn);
    k_split_big <<<dim3(768,12),256>>>(d0w1,d0w2,d1w1,d1w2, wh,wl);
    k_split_small<<<dim3(256,18),256>>>(wf,ent,nw1,nw2, wh,wl);
    k_lin<<<8,256>>>(gp, lin);
    k_init<<<BATCHN*QD/256,256>>>(x, curh, curl);

    for(int li=0;li<8;li++){
        int t=li%3;
        if(t==0){
            int i=li/3;
            gemm(0, curh,curl, wh+O_D0W1+(long)i*196608, wl+O_D0W1+(long)i*196608,
                 d0b1+(long)i*768, h32, nullptr,nullptr, nullptr,nullptr,nullptr,nullptr, 256,768);
            k_ln_gelu<<<BATCHN/8,256>>>(h32, lnw+(long)i*768, lnb+(long)i*768, hh_, hl_);
            gemm(0, hh_,hl_, wh+O_D0W2+(long)i*196608, wl+O_D0W2+(long)i*196608,
                 d0b2+(long)i*256, nullptr, tmph,tmpl, nullptr,nullptr,nullptr,nullptr, 768,256);
        } else if(t==1){
            int i=(li-1)/3;
            gemm(1, curh,curl, wh+O_D1W1+(long)i*131072, wl+O_D1W1+(long)i*131072,
                 d1b1+(long)i*512, nullptr, hh_,hl_, nullptr,nullptr,nullptr,nullptr, 256,512);
            gemm(0, hh_,hl_, wh+O_D1W2+(long)i*131072, wl+O_D1W2+(long)i*131072,
                 d1b2+(long)i*256, nullptr, tmph,tmpl, nullptr,nullptr,nullptr,nullptr, 512,256);
        } else {
            int i=(li-2)/3;
            gemm(0, curh,curl, wh+O_ATT+(long)i*65536, wl+O_ATT+(long)i*65536,
                 battn+(long)i*256, nullptr, tmph,tmpl, nullptr,nullptr,nullptr,nullptr, 256,256);
        }
        // entangle GEMM with fused gate/combine epilogue -> c2 (hi/lo only)
        gemm(3, tmph,tmpl, wh+O_TENT+(long)li*65536, wl+O_TENT+(long)li*65536,
             nullptr, nullptr, c2h,c2l, tmph,tmpl, gp+(long)li*256*6, lin+(long)li*256, 256,256);

        const float* nlptr=nullptr;
        if(li&1){
            int j=li/2;
            gemm(2, c2h,c2l, wh+O_NW1+(long)j*65536, wl+O_NW1+(long)j*65536,
                 nb1+(long)j*256, nullptr, hh_,hl_, nullptr,nullptr,nullptr,nullptr, 256,256);
            gemm(0, hh_,hl_, wh+O_NW2+(long)j*65536, wl+O_NW2+(long)j*65536,
                 nb2+(long)j*256, nl32, nullptr,nullptr, nullptr,nullptr,nullptr,nullptr, 256,256);
            nlptr=nl32;
        }
        float alpha=(li<4)?0.8f:0.6f;
        float* outp=(li==7)?(float*)d_out:nullptr;
        k_final<<<BATCHN/8,256>>>(c2h,c2l, nlptr, curh, curl, outp, alpha);
    }
}

// round 7
// speedup vs baseline: 1.6154x; 1.0632x over previous
#include <cuda_runtime.h>
#include <cuda_bf16.h>
#include <stdint.h>
#include <math.h>

typedef __nv_bfloat16 bf16;
#define BATCHN 65536
#define QD 256

__device__ float g_h32 [(long)BATCHN*768];
__device__ float g_nl32[(long)BATCHN*QD];
__device__ bf16  g_curh[(long)BATCHN*QD],  g_curl[(long)BATCHN*QD];
__device__ bf16  g_hh  [(long)BATCHN*768], g_hl  [(long)BATCHN*768];
__device__ bf16  g_tmph[(long)BATCHN*QD],  g_tmpl[(long)BATCHN*QD];
__device__ bf16  g_c2h [(long)BATCHN*QD],  g_c2l [(long)BATCHN*QD];
__device__ bf16  g_w_h[3145728], g_w_l[3145728];
__device__ float g_wf[2*256*256];
__device__ float g_battn[2*256];
__device__ float g_lin[8*256];

__device__ __forceinline__ void split2(float v, bf16& h, bf16& l){
    h = __float2bfloat16(v);
    l = __float2bfloat16(v - __bfloat162float(h));
}
__device__ __forceinline__ unsigned cvsm(const void* p){
    unsigned a;
    asm("{ .reg .u64 t; cvta.to.shared.u64 t, %1; cvt.u32.u64 %0, t; }" : "=r"(a) : "l"(p));
    return a;
}
__device__ __forceinline__ void ldm4(unsigned a, unsigned& r0, unsigned& r1, unsigned& r2, unsigned& r3){
    asm volatile("ldmatrix.sync.aligned.m8n8.x4.shared.b16 {%0,%1,%2,%3}, [%4];"
                 : "=r"(r0),"=r"(r1),"=r"(r2),"=r"(r3) : "r"(a));
}
__device__ __forceinline__ void mmabf(float* c, const unsigned* a, const unsigned* b){
    asm volatile("mma.sync.aligned.m16n8k16.row.col.f32.bf16.bf16.f32 "
                 "{%0,%1,%2,%3},{%4,%5,%6,%7},{%8,%9},{%0,%1,%2,%3};"
                 : "+f"(c[0]),"+f"(c[1]),"+f"(c[2]),"+f"(c[3])
                 : "r"(a[0]),"r"(a[1]),"r"(a[2]),"r"(a[3]),"r"(b[0]),"r"(b[1]));
}

#define BM 128
#define BN 128
#define BKK 32
#define LDT 40                 // bf16 units; 80B rows; ldmatrix conflict-free
#define ASZ (BM*LDT)           // 5120 bf16 per array
#define STG (4*ASZ)            // Ah,Al,Bh,Bl per stage (bf16 units)
#define SM_TOT (2*STG*2)       // bytes: 2 stages x 40960B = 81920

__device__ __forceinline__ void load_stage(bf16* st,
    const bf16* __restrict__ Ah, const bf16* __restrict__ Al,
    const bf16* __restrict__ Bh, const bf16* __restrict__ Bl,
    long rowBase, int colBase, int K, int k0, int tid)
{
    int r=tid>>2, kc0=(tid&3)<<3;      // 512 threads: 1 uint4 per array each
    long ga=(rowBase+r)*(long)K + k0 + kc0;
    long gb=((long)(colBase+r))*(long)K + k0 + kc0;
    int so=r*LDT+kc0;
    *(uint4*)(st+so)        = *(const uint4*)(Ah+ga);
    *(uint4*)(st+ASZ+so)    = *(const uint4*)(Al+ga);
    *(uint4*)(st+2*ASZ+so)  = *(const uint4*)(Bh+gb);
    *(uint4*)(st+3*ASZ+so)  = *(const uint4*)(Bl+gb);
}

// C[M,N] = epi(A@W + bias). A hi/lo [M][K]; W transposed hi/lo [N][K].
// EPI: 0 none, 1 silu, 2 tanh, 3 fused-combine.
template<int EPI>
__global__ void __launch_bounds__(512,1) gemm_k(
    const bf16* __restrict__ Ah, const bf16* __restrict__ Al,
    const bf16* __restrict__ Bh, const bf16* __restrict__ Bl,
    const float* __restrict__ bias,
    float* __restrict__ C32, bf16* __restrict__ Ch, bf16* __restrict__ Cl,
    const bf16* __restrict__ tmphP, const bf16* __restrict__ tmplP,
    const float* __restrict__ gpP, const float* __restrict__ linP,
    int K, int N)
{
    extern __shared__ bf16 sm[];
    const int tid=threadIdx.x, lane=tid&31, warp=tid>>5;
    const int wm=warp>>2, wn=warp&3;      // 4x4 warp grid, 32x32 warp tiles
    const long rowBase=(long)blockIdx.y*BM;
    const int  colBase=blockIdx.x*BN;

    float acc[2][4][4];
#pragma unroll
    for(int a=0;a<2;a++)
#pragma unroll
    for(int b=0;b<4;b++)
#pragma unroll
    for(int c=0;c<4;c++) acc[a][b][c]=0.f;

    const int nIter=K/BKK;
    load_stage(sm, Ah,Al,Bh,Bl, rowBase,colBase, K, 0, tid);
    __syncthreads();

    for(int i=0;i<nIter;i++){
        bf16* cur = sm + (i&1)*STG;
        if(i+1<nIter)
            load_stage(sm+((i+1)&1)*STG, Ah,Al,Bh,Bl, rowBase,colBase, K, (i+1)*BKK, tid);
        bf16* sAh=cur; bf16* sAl=cur+ASZ; bf16* sBh=cur+2*ASZ; bf16* sBl=cur+3*ASZ;
#pragma unroll
        for(int ks=0;ks<2;ks++){
            unsigned aH[2][4], aL[2][4], bH[4][2], bL[4][2];
            const int colo = ks*16 + ((lane>>4)<<3);
#pragma unroll
            for(int mt=0;mt<2;mt++){
                int row=wm*32+mt*16+(lane&15);
                ldm4(cvsm(sAh+row*LDT+colo), aH[mt][0],aH[mt][1],aH[mt][2],aH[mt][3]);
                ldm4(cvsm(sAl+row*LDT+colo), aL[mt][0],aL[mt][1],aL[mt][2],aL[mt][3]);
            }
#pragma unroll
            for(int np=0;np<2;np++){
                int row=wn*32+np*16+(lane&15);
                unsigned t0,t1,t2,t3;
                ldm4(cvsm(sBh+row*LDT+colo), t0,t1,t2,t3);
                bH[2*np][0]=t0; bH[2*np][1]=t2; bH[2*np+1][0]=t1; bH[2*np+1][1]=t3;
                ldm4(cvsm(sBl+row*LDT+colo), t0,t1,t2,t3);
                bL[2*np][0]=t0; bL[2*np][1]=t2; bL[2*np+1][0]=t1; bL[2*np+1][1]=t3;
            }
#pragma unroll
            for(int mt=0;mt<2;mt++)
#pragma unroll
            for(int nt=0;nt<4;nt++){
                mmabf(acc[mt][nt], aH[mt], bH[nt]);
                mmabf(acc[mt][nt], aH[mt], bL[nt]);
                mmabf(acc[mt][nt], aL[mt], bH[nt]);
            }
        }
        __syncthreads();
    }

#pragma unroll
    for(int mt=0;mt<2;mt++)
#pragma unroll
    for(int nt=0;nt<4;nt++){
        int n0=colBase+wn*32+nt*8+((lane&3)<<1);
        float b0=0.f,b1=0.f;
        if(EPI!=3 && bias){ b0=bias[n0]; b1=bias[n0+1]; }
        float l0=0,p30=0,p40=0,p50=0,l1=0,p31=0,p41=0,p51=0;
        if(EPI==3){
            l0=linP[n0]; p30=gpP[n0*6+3]; p40=gpP[n0*6+4]; p50=gpP[n0*6+5];
            l1=linP[n0+1]; p31=gpP[(n0+1)*6+3]; p41=gpP[(n0+1)*6+4]; p51=gpP[(n0+1)*6+5];
        }
#pragma unroll
        for(int hh=0;hh<2;hh++){
            long row=rowBase+wm*32+mt*16+(lane>>2)+hh*8;
            long o=row*(long)N+n0;
            float v0=acc[mt][nt][2*hh]+b0, v1=acc[mt][nt][2*hh+1]+b1;
            if(EPI==1){ v0*=1.f/(1.f+__expf(-v0)); v1*=1.f/(1.f+__expf(-v1)); }
            if(EPI==2){ v0=tanhf(v0); v1=tanhf(v1); }
            if(EPI==3){
                __nv_bfloat162 th=*(const __nv_bfloat162*)(tmphP+o);
                __nv_bfloat162 tl=*(const __nv_bfloat162*)(tmplP+o);
                float t0v=__bfloat162float(th.x)+__bfloat162float(tl.x);
                float t1v=__bfloat162float(th.y)+__bfloat162float(tl.y);
                float g0=(l0*t0v + 0.5f*sinf(p30*t0v+p40) + 0.5f*cosf(p50*t0v))*0.25f;
                float g1=(l1*t1v + 0.5f*sinf(p31*t1v+p41) + 0.5f*cosf(p51*t1v))*0.25f;
                v0=(t0v + 0.3f*g0 + 0.2f*v0)*(1.0f/1.5f);
                v1=(t1v + 0.3f*g1 + 0.2f*v1)*(1.0f/1.5f);
            }
            if(C32){ float2 f; f.x=v0; f.y=v1; *(float2*)(C32+o)=f; }
            if(Ch){
                bf16 h0,q0,h1,q1; split2(v0,h0,q0); split2(v1,h1,q1);
                __nv_bfloat162 ph,pl; ph.x=h0; ph.y=h1; pl.x=q0; pl.y=q1;
                *(__nv_bfloat162*)(Ch+o)=ph; *(__nv_bfloat162*)(Cl+o)=pl;
            }
        }
    }
}

__global__ void k_init(const float* __restrict__ x,
                       bf16* __restrict__ ch, bf16* __restrict__ cl){
    long idx=(long)blockIdx.x*256+threadIdx.x;
    float v=x[idx];
    bf16 h,l; split2(v,h,l); ch[idx]=h; cl[idx]=l;
}

__device__ __forceinline__ void split_store(const float* W, bf16* oh, bf16* ol,
                                            int K, int N, int do_tanh, long seg, long idx){
    if(idx>=seg) return;
    int k=(int)(idx/N), n=(int)(idx%N);
    float v=W[idx]; if(do_tanh) v=tanhf(v);
    bf16 h,l; split2(v,h,l);
    oh[(long)n*K+k]=h; ol[(long)n*K+k]=l;
}

__global__ void k_split_big(const float* __restrict__ d0w1, const float* __restrict__ d0w2,
                            const float* __restrict__ d1w1, const float* __restrict__ d1w2,
                            bf16* __restrict__ wh, bf16* __restrict__ wl){
    const long O_D0W1=0, O_D0W2=589824, O_D1W1=1179648, O_D1W2=1572864;
    long idx=(long)blockIdx.x*256+threadIdx.x;
    int y=blockIdx.y;
    if(y<3){        long b=(long)y*196608;
        split_store(d0w1+b, wh+O_D0W1+b, wl+O_D0W1+b, 256,768,0,196608,idx);
    } else if(y<6){ long b=(long)(y-3)*196608;
        split_store(d0w2+b, wh+O_D0W2+b, wl+O_D0W2+b, 768,256,0,196608,idx);
    } else if(y<9){ long b=(long)(y-6)*131072;
        split_store(d1w1+b, wh+O_D1W1+b, wl+O_D1W1+b, 256,512,0,131072,idx);
    } else {        long b=(long)(y-9)*131072;
        split_store(d1w2+b, wh+O_D1W2+b, wl+O_D1W2+b, 512,256,0,131072,idx);
    }
}

__global__ void k_split_small(const float* __restrict__ wf, const float* __restrict__ ent,
                              const float* __restrict__ nw1, const float* __restrict__ nw2,
                              bf16* __restrict__ wh, bf16* __restrict__ wl){
    const long O_ATT=1966080, O_TENT=2097152, O_NW1=2621440, O_NW2=2883584;
    long idx=(long)blockIdx.x*256+threadIdx.x;
    int y=blockIdx.y;
    if(y<2){         long b=(long)y*65536;
        split_store(wf+b,  wh+O_ATT+b,  wl+O_ATT+b,  256,256,0,65536,idx);
    } else if(y<10){ long b=(long)(y-2)*65536;
        split_store(ent+b, wh+O_TENT+b, wl+O_TENT+b, 256,256,1,65536,idx);
    } else if(y<14){ long b=(long)(y-10)*65536;
        split_store(nw1+b, wh+O_NW1+b,  wl+O_NW1+b,  256,256,0,65536,idx);
    } else {         long b=(long)(y-14)*65536;
        split_store(nw2+b, wh+O_NW2+b,  wl+O_NW2+b,  256,256,0,65536,idx);
    }
}

__global__ void k_attn_fuse(const float* __restrict__ wqkv, const float* __restrict__ bqkv,
                            const float* __restrict__ wo, const float* __restrict__ bo,
                            float* __restrict__ wf, float* __restrict__ battn){
    int i=blockIdx.y;
    int idx=blockIdx.x*256+threadIdx.x;
    int k=idx>>8, n=idx&255;
    const float* Wv=wqkv+(long)i*256*768+512;
    const float* Wo=wo+(long)i*256*256;
    float s=0.f;
    for(int j=0;j<256;j++) s+=Wv[(long)k*768+j]*Wo[(long)j*256+n];
    wf[(long)i*65536+idx]=s;
    if(k==0){
        float sb=bo[i*256+n];
        for(int j=0;j<256;j++) sb+=bqkv[(long)i*768+512+j]*Wo[(long)j*256+n];
        battn[i*256+n]=sb;
    }
}

__global__ void k_lin(const float* __restrict__ gp, float* __restrict__ lin){
    int idx=blockIdx.x*256+threadIdx.x;
    const float* p=gp+(long)idx*6;
    lin[idx]=sinf(p[0])+cosf(p[1])+tanhf(p[2]);
}

__global__ void k_ln_gelu(const float* __restrict__ h, const float* __restrict__ w, const float* __restrict__ b,
                          bf16* __restrict__ oh, bf16* __restrict__ ol){
    int row=blockIdx.x*8+(threadIdx.x>>5);
    int lane=threadIdx.x&31;
    const float* hr=h+(long)row*768;
    float v[24]; float s=0.f,s2=0.f;
#pragma unroll
    for(int j=0;j<24;j++){ float x=hr[lane+32*j]; v[j]=x; s+=x; s2+=x*x; }
#pragma unroll
    for(int o=16;o;o>>=1){ s+=__shfl_xor_sync(0xffffffffu,s,o); s2+=__shfl_xor_sync(0xffffffffu,s2,o); }
    float mu=s*(1.f/768.f);
    float var=s2*(1.f/768.f)-mu*mu;
    float inv=rsqrtf(var+1e-5f);
    long base=(long)row*768;
#pragma unroll
    for(int j=0;j<24;j++){
        int q=lane+32*j;
        float y=(v[j]-mu)*inv*w[q]+b[q];
        float g=0.5f*y*(1.f+erff(y*0.70710678118654752f));
        bf16 hh,ll; split2(g,hh,ll);
        oh[base+q]=hh; ol[base+q]=ll;
    }
}

__global__ void k_final(const bf16* __restrict__ c2h, const bf16* __restrict__ c2l,
                        const float* __restrict__ nl,
                        bf16* __restrict__ ch, bf16* __restrict__ cl,
                        float* __restrict__ outp, float alpha){
    int row=blockIdx.x*8+(threadIdx.x>>5);
    int lane=threadIdx.x&31;
    long base=(long)row*QD;
    float v[8]; float ss=0.f;
#pragma unroll
    for(int j=0;j<8;j++){
        int q=lane+32*j;
        float x=__bfloat162float(c2h[base+q])+__bfloat162float(c2l[base+q]);
        if(nl) x+=0.1f*nl[base+q];
        float res=__bfloat162float(ch[base+q])+__bfloat162float(cl[base+q]);
        float y=alpha*x+(1.f-alpha)*res;
        v[j]=y; ss+=y*y;
    }
#pragma unroll
    for(int o=16;o;o>>=1) ss+=__shfl_xor_sync(0xffffffffu,ss,o);
    float inv=1.f/(sqrtf(ss)+1e-8f);
#pragma unroll
    for(int j=0;j<8;j++){
        int q=lane+32*j;
        float y=tanhf(v[j]*inv);
        if(outp) outp[base+q]=y;
        else{ bf16 h,l; split2(y,h,l); ch[base+q]=h; cl[base+q]=l; }
    }
}

static void* symaddr(const void* s){ void* p=nullptr; cudaGetSymbolAddress(&p, s); return p; }

static void gemm(int epi, const bf16* Ah,const bf16* Al,const bf16* Bh,const bf16* Bl,
                 const float* bias, float* C32, bf16* Ch, bf16* Cl,
                 const bf16* tmphP, const bf16* tmplP, const float* gpP, const float* linP,
                 int K,int N){
    dim3 grid(N/128, BATCHN/128);
    if(epi==0)      gemm_k<0><<<grid,512,SM_TOT>>>(Ah,Al,Bh,Bl,bias,C32,Ch,Cl,tmphP,tmplP,gpP,linP,K,N);
    else if(epi==1) gemm_k<1><<<grid,512,SM_TOT>>>(Ah,Al,Bh,Bl,bias,C32,Ch,Cl,tmphP,tmplP,gpP,linP,K,N);
    else if(epi==2) gemm_k<2><<<grid,512,SM_TOT>>>(Ah,Al,Bh,Bl,bias,C32,Ch,Cl,tmphP,tmplP,gpP,linP,K,N);
    else            gemm_k<3><<<grid,512,SM_TOT>>>(Ah,Al,Bh,Bl,bias,C32,Ch,Cl,tmphP,tmplP,gpP,linP,K,N);
}

extern "C" void kernel_launch(void* const* d_in, const int* in_sizes, int n_in,
                              void* d_out, int out_size){
    (void)in_sizes;(void)n_in;(void)out_size;
    cudaFuncSetAttribute(gemm_k<0>, cudaFuncAttributeMaxDynamicSharedMemorySize, SM_TOT);
    cudaFuncSetAttribute(gemm_k<1>, cudaFuncAttributeMaxDynamicSharedMemorySize, SM_TOT);
    cudaFuncSetAttribute(gemm_k<2>, cudaFuncAttributeMaxDynamicSharedMemorySize, SM_TOT);
    cudaFuncSetAttribute(gemm_k<3>, cudaFuncAttributeMaxDynamicSharedMemorySize, SM_TOT);

    const float* x   =(const float*)d_in[0];
    const float* d0w1=(const float*)d_in[1];
    const float* d0b1=(const float*)d_in[2];
    const float* lnw =(const float*)d_in[3];
    const float* lnb =(const float*)d_in[4];
    const float* d0w2=(const float*)d_in[5];
    const float* d0b2=(const float*)d_in[6];
    const float* d1w1=(const float*)d_in[7];
    const float* d1b1=(const float*)d_in[8];
    const float* d1w2=(const float*)d_in[9];
    const float* d1b2=(const float*)d_in[10];
    const float* wqkv=(const float*)d_in[11];
    const float* bqkv=(const float*)d_in[12];
    const float* wo  =(const float*)d_in[13];
    const float* bo  =(const float*)d_in[14];
    const float* gp  =(const float*)d_in[15];
    const float* ent =(const float*)d_in[16];
    const float* nw1 =(const float*)d_in[17];
    const float* nb1 =(const float*)d_in[18];
    const float* nw2 =(const float*)d_in[19];
    const float* nb2 =(const float*)d_in[20];

    float* h32  =(float*)symaddr(g_h32);
    float* nl32 =(float*)symaddr(g_nl32);
    bf16* curh=(bf16*)symaddr(g_curh); bf16* curl=(bf16*)symaddr(g_curl);
    bf16* hh_ =(bf16*)symaddr(g_hh);   bf16* hl_ =(bf16*)symaddr(g_hl);
    bf16* tmph=(bf16*)symaddr(g_tmph); bf16* tmpl=(bf16*)symaddr(g_tmpl);
    bf16* c2h =(bf16*)symaddr(g_c2h);  bf16* c2l =(bf16*)symaddr(g_c2l);
    bf16* wh  =(bf16*)symaddr(g_w_h);  bf16* wl  =(bf16*)symaddr(g_w_l);
    float* wf   =(float*)symaddr(g_wf);
    float* battn=(float*)symaddr(g_battn);
    float* lin  =(float*)symaddr(g_lin);

    const long O_D0W1=0, O_D0W2=589824, O_D1W1=1179648, O_D1W2=1572864;
    const long O_ATT=1966080, O_TENT=2097152, O_NW1=2621440, O_NW2=2883584;

    // minimal prep before first GEMM so ncu's skip window lands on a main GEMM
    k_split_big <<<dim3(768,12),256>>>(d0w1,d0w2,d1w1,d1w2, wh,wl);
    k_init<<<BATCHN*QD/256,256>>>(x, curh, curl);

    for(int li=0;li<8;li++){
        int t=li%3;
        if(t==0){
            int i=li/3;
            gemm(0, curh,curl, wh+O_D0W1+(long)i*196608, wl+O_D0W1+(long)i*196608,
                 d0b1+(long)i*768, h32, nullptr,nullptr, nullptr,nullptr,nullptr,nullptr, 256,768);
            k_ln_gelu<<<BATCHN/8,256>>>(h32, lnw+(long)i*768, lnb+(long)i*768, hh_, hl_);
            gemm(0, hh_,hl_, wh+O_D0W2+(long)i*196608, wl+O_D0W2+(long)i*196608,
                 d0b2+(long)i*256, nullptr, tmph,tmpl, nullptr,nullptr,nullptr,nullptr, 768,256);
        } else if(t==1){
            int i=(li-1)/3;
            gemm(1, curh,curl, wh+O_D1W1+(long)i*131072, wl+O_D1W1+(long)i*131072,
                 d1b1+(long)i*512, nullptr, hh_,hl_, nullptr,nullptr,nullptr,nullptr, 256,512);
            gemm(0, hh_,hl_, wh+O_D1W2+(long)i*131072, wl+O_D1W2+(long)i*131072,
                 d1b2+(long)i*256, nullptr, tmph,tmpl, nullptr,nullptr,nullptr,nullptr, 512,256);
        } else {
            int i=(li-2)/3;
            gemm(0, curh,curl, wh+O_ATT+(long)i*65536, wl+O_ATT+(long)i*65536,
                 battn+(long)i*256, nullptr, tmph,tmpl, nullptr,nullptr,nullptr,nullptr, 256,256);
        }
        if(li==0){
            // deferred prep (first needed by the entangle GEMM below / attn at li=2)
            k_attn_fuse <<<dim3(256,2),256>>>(wqkv,bqkv,wo,bo,wf,battn);
            k_split_small<<<dim3(256,18),256>>>(wf,ent,nw1,nw2, wh,wl);
            k_lin<<<8,256>>>(gp, lin);
        }
        gemm(3, tmph,tmpl, wh+O_TENT+(long)li*65536, wl+O_TENT+(long)li*65536,
             nullptr, nullptr, c2h,c2l, tmph,tmpl, gp+(long)li*256*6, lin+(long)li*256, 256,256);

        const float* nlptr=nullptr;
        if(li&1){
            int j=li/2;
            gemm(2, c2h,c2l, wh+O_NW1+(long)j*65536, wl+O_NW1+(long)j*65536,
                 nb1+(long)j*256, nullptr, hh_,hl_, nullptr,nullptr,nullptr,nullptr, 256,256);
            gemm(0, hh_,hl_, wh+O_NW2+(long)j*65536, wl+O_NW2+(long)j*65536,
                 nb2+(long)j*256, nl32, nullptr,nullptr, nullptr,nullptr,nullptr,nullptr, 256,256);
            nlptr=nl32;
        }
        float alpha=(li<4)?0.8f:0.6f;
        float* outp=(li==7)?(float*)d_out:nullptr;
        k_final<<<BATCHN/8,256>>>(c2h,c2l, nlptr, curh, curl, outp, alpha);
    }
}

// round 8
// speedup vs baseline: 1.7598x; 1.0894x over previous
#include <cuda_runtime.h>
#include <cuda_bf16.h>
#include <stdint.h>
#include <math.h>

typedef __nv_bfloat16 bf16;
#define BATCHN 65536
#define QD 256

__device__ float g_h32 [(long)BATCHN*768];
__device__ float g_nl32[(long)BATCHN*QD];
__device__ bf16  g_curh[(long)BATCHN*QD],  g_curl[(long)BATCHN*QD];
__device__ bf16  g_hh  [(long)BATCHN*768], g_hl  [(long)BATCHN*768];
__device__ bf16  g_tmph[(long)BATCHN*QD],  g_tmpl[(long)BATCHN*QD];
__device__ bf16  g_c2h [(long)BATCHN*QD],  g_c2l [(long)BATCHN*QD];
__device__ bf16  g_w_h[3145728], g_w_l[3145728];
__device__ float g_wf[2*256*256];
__device__ float g_battn[2*256];
__device__ float g_lin[8*256];

__device__ __forceinline__ void split2(float v, bf16& h, bf16& l){
    h = __float2bfloat16(v);
    l = __float2bfloat16(v - __bfloat162float(h));
}
__device__ __forceinline__ unsigned cvsm(const void* p){
    unsigned a;
    asm("{ .reg .u64 t; cvta.to.shared.u64 t, %1; cvt.u32.u64 %0, t; }" : "=r"(a) : "l"(p));
    return a;
}
__device__ __forceinline__ void ldm4(unsigned a, unsigned& r0, unsigned& r1, unsigned& r2, unsigned& r3){
    asm volatile("ldmatrix.sync.aligned.m8n8.x4.shared.b16 {%0,%1,%2,%3}, [%4];"
                 : "=r"(r0),"=r"(r1),"=r"(r2),"=r"(r3) : "r"(a));
}
__device__ __forceinline__ void mmabf(float* c, const unsigned* a, const unsigned* b){
    asm volatile("mma.sync.aligned.m16n8k16.row.col.f32.bf16.bf16.f32 "
                 "{%0,%1,%2,%3},{%4,%5,%6,%7},{%8,%9},{%0,%1,%2,%3};"
                 : "+f"(c[0]),"+f"(c[1]),"+f"(c[2]),"+f"(c[3])
                 : "r"(a[0]),"r"(a[1]),"r"(a[2]),"r"(a[3]),"r"(b[0]),"r"(b[1]));
}

#define BM 128
#define BN 128
#define BKK 64
#define LDT 72                 // bf16 units; 144B rows (16 mod 128 -> conflict-free)
#define ASZ (BM*LDT)           // 9216 bf16 per array
#define STG (4*ASZ)            // Ah,Al,Bh,Bl per stage (bf16 units)
#define SM_TOT (2*STG*2)       // bytes: 2 stages x 73728B = 147456

__device__ __forceinline__ void load_stage(bf16* st,
    const bf16* __restrict__ Ah, const bf16* __restrict__ Al,
    const bf16* __restrict__ Bh, const bf16* __restrict__ Bl,
    long rowBase, int colBase, int K, int k0, int tid)
{
#pragma unroll
    for(int it=0; it<2; it++){
        int j = tid + (it<<9);              // 0..1023
        int r = j>>3, kc0=(j&7)<<3;         // row 0..127, col 0..56
        long ga=(rowBase+r)*(long)K + k0 + kc0;
        long gb=((long)(colBase+r))*(long)K + k0 + kc0;
        int so=r*LDT+kc0;
        *(uint4*)(st+so)        = *(const uint4*)(Ah+ga);
        *(uint4*)(st+ASZ+so)    = *(const uint4*)(Al+ga);
        *(uint4*)(st+2*ASZ+so)  = *(const uint4*)(Bh+gb);
        *(uint4*)(st+3*ASZ+so)  = *(const uint4*)(Bl+gb);
    }
}

// C[M,N] = epi(A@W + bias). A hi/lo [M][K]; W transposed hi/lo [N][K].
// EPI: 0 none, 1 silu, 2 tanh, 3 fused-combine.
template<int EPI>
__global__ void __launch_bounds__(512,1) gemm_k(
    const bf16* __restrict__ Ah, const bf16* __restrict__ Al,
    const bf16* __restrict__ Bh, const bf16* __restrict__ Bl,
    const float* __restrict__ bias,
    float* __restrict__ C32, bf16* __restrict__ Ch, bf16* __restrict__ Cl,
    const bf16* __restrict__ tmphP, const bf16* __restrict__ tmplP,
    const float* __restrict__ gpP, const float* __restrict__ linP,
    int K, int N)
{
    extern __shared__ bf16 sm[];
    const int tid=threadIdx.x, lane=tid&31, warp=tid>>5;
    const int wm=warp>>2, wn=warp&3;      // 4x4 warp grid, 32x32 warp tiles
    const long rowBase=(long)blockIdx.y*BM;
    const int  colBase=blockIdx.x*BN;

    float acc[2][4][4];
#pragma unroll
    for(int a=0;a<2;a++)
#pragma unroll
    for(int b=0;b<4;b++)
#pragma unroll
    for(int c=0;c<4;c++) acc[a][b][c]=0.f;

    const int nIter=K/BKK;
    load_stage(sm, Ah,Al,Bh,Bl, rowBase,colBase, K, 0, tid);
    __syncthreads();

    for(int i=0;i<nIter;i++){
        bf16* cur = sm + (i&1)*STG;
        if(i+1<nIter)
            load_stage(sm+((i+1)&1)*STG, Ah,Al,Bh,Bl, rowBase,colBase, K, (i+1)*BKK, tid);
        bf16* sAh=cur; bf16* sAl=cur+ASZ; bf16* sBh=cur+2*ASZ; bf16* sBl=cur+3*ASZ;
#pragma unroll
        for(int ks=0;ks<4;ks++){
            unsigned aH[2][4], aL[2][4], bH[4][2], bL[4][2];
            const int colo = ks*16 + ((lane>>4)<<3);
#pragma unroll
            for(int mt=0;mt<2;mt++){
                int row=wm*32+mt*16+(lane&15);
                ldm4(cvsm(sAh+row*LDT+colo), aH[mt][0],aH[mt][1],aH[mt][2],aH[mt][3]);
                ldm4(cvsm(sAl+row*LDT+colo), aL[mt][0],aL[mt][1],aL[mt][2],aL[mt][3]);
            }
#pragma unroll
            for(int np=0;np<2;np++){
                int row=wn*32+np*16+(lane&15);
                unsigned t0,t1,t2,t3;
                ldm4(cvsm(sBh+row*LDT+colo), t0,t1,t2,t3);
                bH[2*np][0]=t0; bH[2*np][1]=t2; bH[2*np+1][0]=t1; bH[2*np+1][1]=t3;
                ldm4(cvsm(sBl+row*LDT+colo), t0,t1,t2,t3);
                bL[2*np][0]=t0; bL[2*np][1]=t2; bL[2*np+1][0]=t1; bL[2*np+1][1]=t3;
            }
#pragma unroll
            for(int mt=0;mt<2;mt++)
#pragma unroll
            for(int nt=0;nt<4;nt++){
                mmabf(acc[mt][nt], aH[mt], bH[nt]);
                mmabf(acc[mt][nt], aH[mt], bL[nt]);
                mmabf(acc[mt][nt], aL[mt], bH[nt]);
            }
        }
        __syncthreads();
    }

#pragma unroll
    for(int mt=0;mt<2;mt++)
#pragma unroll
    for(int nt=0;nt<4;nt++){
        int n0=colBase+wn*32+nt*8+((lane&3)<<1);
        float b0=0.f,b1=0.f;
        if(EPI!=3 && bias){ b0=bias[n0]; b1=bias[n0+1]; }
        float l0=0,p30=0,p40=0,p50=0,l1=0,p31=0,p41=0,p51=0;
        if(EPI==3){
            l0=linP[n0]; p30=gpP[n0*6+3]; p40=gpP[n0*6+4]; p50=gpP[n0*6+5];
            l1=linP[n0+1]; p31=gpP[(n0+1)*6+3]; p41=gpP[(n0+1)*6+4]; p51=gpP[(n0+1)*6+5];
        }
#pragma unroll
        for(int hh=0;hh<2;hh++){
            long row=rowBase+wm*32+mt*16+(lane>>2)+hh*8;
            long o=row*(long)N+n0;
            float v0=acc[mt][nt][2*hh]+b0, v1=acc[mt][nt][2*hh+1]+b1;
            if(EPI==1){ v0*=1.f/(1.f+__expf(-v0)); v1*=1.f/(1.f+__expf(-v1)); }
            if(EPI==2){ v0=tanhf(v0); v1=tanhf(v1); }
            if(EPI==3){
                __nv_bfloat162 th=*(const __nv_bfloat162*)(tmphP+o);
                __nv_bfloat162 tl=*(const __nv_bfloat162*)(tmplP+o);
                float t0v=__bfloat162float(th.x)+__bfloat162float(tl.x);
                float t1v=__bfloat162float(th.y)+__bfloat162float(tl.y);
                float g0=(l0*t0v + 0.5f*sinf(p30*t0v+p40) + 0.5f*cosf(p50*t0v))*0.25f;
                float g1=(l1*t1v + 0.5f*sinf(p31*t1v+p41) + 0.5f*cosf(p51*t1v))*0.25f;
                v0=(t0v + 0.3f*g0 + 0.2f*v0)*(1.0f/1.5f);
                v1=(t1v + 0.3f*g1 + 0.2f*v1)*(1.0f/1.5f);
            }
            if(C32){ float2 f; f.x=v0; f.y=v1; *(float2*)(C32+o)=f; }
            if(Ch){
                bf16 h0,q0,h1,q1; split2(v0,h0,q0); split2(v1,h1,q1);
                __nv_bfloat162 ph,pl; ph.x=h0; ph.y=h1; pl.x=q0; pl.y=q1;
                *(__nv_bfloat162*)(Ch+o)=ph; *(__nv_bfloat162*)(Cl+o)=pl;
            }
        }
    }
}

__global__ void k_init(const float* __restrict__ x,
                       bf16* __restrict__ ch, bf16* __restrict__ cl){
    long idx=(long)blockIdx.x*256+threadIdx.x;
    float v=x[idx];
    bf16 h,l; split2(v,h,l); ch[idx]=h; cl[idx]=l;
}

__device__ __forceinline__ void split_store(const float* W, bf16* oh, bf16* ol,
                                            int K, int N, int do_tanh, long seg, long idx){
    if(idx>=seg) return;
    int k=(int)(idx/N), n=(int)(idx%N);
    float v=W[idx]; if(do_tanh) v=tanhf(v);
    bf16 h,l; split2(v,h,l);
    oh[(long)n*K+k]=h; ol[(long)n*K+k]=l;
}

__global__ void k_split_big(const float* __restrict__ d0w1, const float* __restrict__ d0w2,
                            const float* __restrict__ d1w1, const float* __restrict__ d1w2,
                            bf16* __restrict__ wh, bf16* __restrict__ wl){
    const long O_D0W1=0, O_D0W2=589824, O_D1W1=1179648, O_D1W2=1572864;
    long idx=(long)blockIdx.x*256+threadIdx.x;
    int y=blockIdx.y;
    if(y<3){        long b=(long)y*196608;
        split_store(d0w1+b, wh+O_D0W1+b, wl+O_D0W1+b, 256,768,0,196608,idx);
    } else if(y<6){ long b=(long)(y-3)*196608;
        split_store(d0w2+b, wh+O_D0W2+b, wl+O_D0W2+b, 768,256,0,196608,idx);
    } else if(y<9){ long b=(long)(y-6)*131072;
        split_store(d1w1+b, wh+O_D1W1+b, wl+O_D1W1+b, 256,512,0,131072,idx);
    } else {        long b=(long)(y-9)*131072;
        split_store(d1w2+b, wh+O_D1W2+b, wl+O_D1W2+b, 512,256,0,131072,idx);
    }
}

__global__ void k_split_small(const float* __restrict__ wf, const float* __restrict__ ent,
                              const float* __restrict__ nw1, const float* __restrict__ nw2,
                              bf16* __restrict__ wh, bf16* __restrict__ wl){
    const long O_ATT=1966080, O_TENT=2097152, O_NW1=2621440, O_NW2=2883584;
    long idx=(long)blockIdx.x*256+threadIdx.x;
    int y=blockIdx.y;
    if(y<2){         long b=(long)y*65536;
        split_store(wf+b,  wh+O_ATT+b,  wl+O_ATT+b,  256,256,0,65536,idx);
    } else if(y<10){ long b=(long)(y-2)*65536;
        split_store(ent+b, wh+O_TENT+b, wl+O_TENT+b, 256,256,1,65536,idx);
    } else if(y<14){ long b=(long)(y-10)*65536;
        split_store(nw1+b, wh+O_NW1+b,  wl+O_NW1+b,  256,256,0,65536,idx);
    } else {         long b=(long)(y-14)*65536;
        split_store(nw2+b, wh+O_NW2+b,  wl+O_NW2+b,  256,256,0,65536,idx);
    }
}

__global__ void k_attn_fuse(const float* __restrict__ wqkv, const float* __restrict__ bqkv,
                            const float* __restrict__ wo, const float* __restrict__ bo,
                            float* __restrict__ wf, float* __restrict__ battn){
    int i=blockIdx.y;
    int idx=blockIdx.x*256+threadIdx.x;
    int k=idx>>8, n=idx&255;
    const float* Wv=wqkv+(long)i*256*768+512;
    const float* Wo=wo+(long)i*256*256;
    float s=0.f;
    for(int j=0;j<256;j++) s+=Wv[(long)k*768+j]*Wo[(long)j*256+n];
    wf[(long)i*65536+idx]=s;
    if(k==0){
        float sb=bo[i*256+n];
        for(int j=0;j<256;j++) sb+=bqkv[(long)i*768+512+j]*Wo[(long)j*256+n];
        battn[i*256+n]=sb;
    }
}

__global__ void k_lin(const float* __restrict__ gp, float* __restrict__ lin){
    int idx=blockIdx.x*256+threadIdx.x;
    const float* p=gp+(long)idx*6;
    lin[idx]=sinf(p[0])+cosf(p[1])+tanhf(p[2]);
}

__global__ void k_ln_gelu(const float* __restrict__ h, const float* __restrict__ w, const float* __restrict__ b,
                          bf16* __restrict__ oh, bf16* __restrict__ ol){
    int row=blockIdx.x*8+(threadIdx.x>>5);
    int lane=threadIdx.x&31;
    const float* hr=h+(long)row*768;
    float v[24]; float s=0.f,s2=0.f;
#pragma unroll
    for(int j=0;j<24;j++){ float x=hr[lane+32*j]; v[j]=x; s+=x; s2+=x*x; }
#pragma unroll
    for(int o=16;o;o>>=1){ s+=__shfl_xor_sync(0xffffffffu,s,o); s2+=__shfl_xor_sync(0xffffffffu,s2,o); }
    float mu=s*(1.f/768.f);
    float var=s2*(1.f/768.f)-mu*mu;
    float inv=rsqrtf(var+1e-5f);
    long base=(long)row*768;
#pragma unroll
    for(int j=0;j<24;j++){
        int q=lane+32*j;
        float y=(v[j]-mu)*inv*w[q]+b[q];
        float g=0.5f*y*(1.f+erff(y*0.70710678118654752f));
        bf16 hh,ll; split2(g,hh,ll);
        oh[base+q]=hh; ol[base+q]=ll;
    }
}

__global__ void k_final(const bf16* __restrict__ c2h, const bf16* __restrict__ c2l,
                        const float* __restrict__ nl,
                        bf16* __restrict__ ch, bf16* __restrict__ cl,
                        float* __restrict__ outp, float alpha){
    int row=blockIdx.x*8+(threadIdx.x>>5);
    int lane=threadIdx.x&31;
    long base=(long)row*QD;
    float v[8]; float ss=0.f;
#pragma unroll
    for(int j=0;j<8;j++){
        int q=lane+32*j;
        float x=__bfloat162float(c2h[base+q])+__bfloat162float(c2l[base+q]);
        if(nl) x+=0.1f*nl[base+q];
        float res=__bfloat162float(ch[base+q])+__bfloat162float(cl[base+q]);
        float y=alpha*x+(1.f-alpha)*res;
        v[j]=y; ss+=y*y;
    }
#pragma unroll
    for(int o=16;o;o>>=1) ss+=__shfl_xor_sync(0xffffffffu,ss,o);
    float inv=1.f/(sqrtf(ss)+1e-8f);
#pragma unroll
    for(int j=0;j<8;j++){
        int q=lane+32*j;
        float y=tanhf(v[j]*inv);
        if(outp) outp[base+q]=y;
        else{ bf16 h,l; split2(y,h,l); ch[base+q]=h; cl[base+q]=l; }
    }
}

static void* symaddr(const void* s){ void* p=nullptr; cudaGetSymbolAddress(&p, s); return p; }

static void gemm(int epi, const bf16* Ah,const bf16* Al,const bf16* Bh,const bf16* Bl,
                 const float* bias, float* C32, bf16* Ch, bf16* Cl,
                 const bf16* tmphP, const bf16* tmplP, const float* gpP, const float* linP,
                 int K,int N){
    dim3 grid(N/128, BATCHN/128);
    if(epi==0)      gemm_k<0><<<grid,512,SM_TOT>>>(Ah,Al,Bh,Bl,bias,C32,Ch,Cl,tmphP,tmplP,gpP,linP,K,N);
    else if(epi==1) gemm_k<1><<<grid,512,SM_TOT>>>(Ah,Al,Bh,Bl,bias,C32,Ch,Cl,tmphP,tmplP,gpP,linP,K,N);
    else if(epi==2) gemm_k<2><<<grid,512,SM_TOT>>>(Ah,Al,Bh,Bl,bias,C32,Ch,Cl,tmphP,tmplP,gpP,linP,K,N);
    else            gemm_k<3><<<grid,512,SM_TOT>>>(Ah,Al,Bh,Bl,bias,C32,Ch,Cl,tmphP,tmplP,gpP,linP,K,N);
}

extern "C" void kernel_launch(void* const* d_in, const int* in_sizes, int n_in,
                              void* d_out, int out_size){
    (void)in_sizes;(void)n_in;(void)out_size;
    cudaFuncSetAttribute(gemm_k<0>, cudaFuncAttributeMaxDynamicSharedMemorySize, SM_TOT);
    cudaFuncSetAttribute(gemm_k<1>, cudaFuncAttributeMaxDynamicSharedMemorySize, SM_TOT);
    cudaFuncSetAttribute(gemm_k<2>, cudaFuncAttributeMaxDynamicSharedMemorySize, SM_TOT);
    cudaFuncSetAttribute(gemm_k<3>, cudaFuncAttributeMaxDynamicSharedMemorySize, SM_TOT);

    const float* x   =(const float*)d_in[0];
    const float* d0w1=(const float*)d_in[1];
    const float* d0b1=(const float*)d_in[2];
    const float* lnw =(const float*)d_in[3];
    const float* lnb =(const float*)d_in[4];
    const float* d0w2=(const float*)d_in[5];
    const float* d0b2=(const float*)d_in[6];
    const float* d1w1=(const float*)d_in[7];
    const float* d1b1=(const float*)d_in[8];
    const float* d1w2=(const float*)d_in[9];
    const float* d1b2=(const float*)d_in[10];
    const float* wqkv=(const float*)d_in[11];
    const float* bqkv=(const float*)d_in[12];
    const float* wo  =(const float*)d_in[13];
    const float* bo  =(const float*)d_in[14];
    const float* gp  =(const float*)d_in[15];
    const float* ent =(const float*)d_in[16];
    const float* nw1 =(const float*)d_in[17];
    const float* nb1 =(const float*)d_in[18];
    const float* nw2 =(const float*)d_in[19];
    const float* nb2 =(const float*)d_in[20];

    float* h32  =(float*)symaddr(g_h32);
    float* nl32 =(float*)symaddr(g_nl32);
    bf16* curh=(bf16*)symaddr(g_curh); bf16* curl=(bf16*)symaddr(g_curl);
    bf16* hh_ =(bf16*)symaddr(g_hh);   bf16* hl_ =(bf16*)symaddr(g_hl);
    bf16* tmph=(bf16*)symaddr(g_tmph); bf16* tmpl=(bf16*)symaddr(g_tmpl);
    bf16* c2h =(bf16*)symaddr(g_c2h);  bf16* c2l =(bf16*)symaddr(g_c2l);
    bf16* wh  =(bf16*)symaddr(g_w_h);  bf16* wl  =(bf16*)symaddr(g_w_l);
    float* wf   =(float*)symaddr(g_wf);
    float* battn=(float*)symaddr(g_battn);
    float* lin  =(float*)symaddr(g_lin);

    const long O_D0W1=0, O_D0W2=589824, O_D1W1=1179648, O_D1W2=1572864;
    const long O_ATT=1966080, O_TENT=2097152, O_NW1=2621440, O_NW2=2883584;

    // launches 1-3 are prep; launch #4 is the first main GEMM (ncu profiles #4)
    k_split_big <<<dim3(768,12),256>>>(d0w1,d0w2,d1w1,d1w2, wh,wl);
    k_init<<<BATCHN*QD/256,256>>>(x, curh, curl);
    k_attn_fuse <<<dim3(256,2),256>>>(wqkv,bqkv,wo,bo,wf,battn);

    for(int li=0;li<8;li++){
        int t=li%3;
        if(t==0){
            int i=li/3;
            gemm(0, curh,curl, wh+O_D0W1+(long)i*196608, wl+O_D0W1+(long)i*196608,
                 d0b1+(long)i*768, h32, nullptr,nullptr, nullptr,nullptr,nullptr,nullptr, 256,768);
            if(li==0){
                k_split_small<<<dim3(256,18),256>>>(wf,ent,nw1,nw2, wh,wl);
                k_lin<<<8,256>>>(gp, lin);
            }
            k_ln_gelu<<<BATCHN/8,256>>>(h32, lnw+(long)i*768, lnb+(long)i*768, hh_, hl_);
            gemm(0, hh_,hl_, wh+O_D0W2+(long)i*196608, wl+O_D0W2+(long)i*196608,
                 d0b2+(long)i*256, nullptr, tmph,tmpl, nullptr,nullptr,nullptr,nullptr, 768,256);
        } else if(t==1){
            int i=(li-1)/3;
            gemm(1, curh,curl, wh+O_D1W1+(long)i*131072, wl+O_D1W1+(long)i*131072,
                 d1b1+(long)i*512, nullptr, hh_,hl_, nullptr,nullptr,nullptr,nullptr, 256,512);
            gemm(0, hh_,hl_, wh+O_D1W2+(long)i*131072, wl+O_D1W2+(long)i*131072,
                 d1b2+(long)i*256, nullptr, tmph,tmpl, nullptr,nullptr,nullptr,nullptr, 512,256);
        } else {
            int i=(li-2)/3;
            gemm(0, curh,curl, wh+O_ATT+(long)i*65536, wl+O_ATT+(long)i*65536,
                 battn+(long)i*256, nullptr, tmph,tmpl, nullptr,nullptr,nullptr,nullptr, 256,256);
        }
        gemm(3, tmph,tmpl, wh+O_TENT+(long)li*65536, wl+O_TENT+(long)li*65536,
             nullptr, nullptr, c2h,c2l, tmph,tmpl, gp+(long)li*256*6, lin+(long)li*256, 256,256);

        const float* nlptr=nullptr;
        if(li&1){
            int j=li/2;
            gemm(2, c2h,c2l, wh+O_NW1+(long)j*65536, wl+O_NW1+(long)j*65536,
                 nb1+(long)j*256, nullptr, hh_,hl_, nullptr,nullptr,nullptr,nullptr, 256,256);
            gemm(0, hh_,hl_, wh+O_NW2+(long)j*65536, wl+O_NW2+(long)j*65536,
                 nb2+(long)j*256, nl32, nullptr,nullptr, nullptr,nullptr,nullptr,nullptr, 256,256);
            nlptr=nl32;
        }
        float alpha=(li<4)?0.8f:0.6f;
        float* outp=(li==7)?(float*)d_out:nullptr;
        k_final<<<BATCHN/8,256>>>(c2h,c2l, nlptr, curh, curl, outp, alpha);
    }
}

// round 9
// speedup vs baseline: 1.9906x; 1.1311x over previous
#include <cuda_runtime.h>
#include <cuda_bf16.h>
#include <stdint.h>
#include <math.h>

typedef __nv_bfloat16 bf16;
#define BATCHN 65536
#define QD 256

__device__ float g_h32 [(long)BATCHN*768];
__device__ float g_nl32[(long)BATCHN*QD];
__device__ bf16  g_curh[(long)BATCHN*QD],  g_curl[(long)BATCHN*QD];
__device__ bf16  g_hh  [(long)BATCHN*768], g_hl  [(long)BATCHN*768];
__device__ bf16  g_tmph[(long)BATCHN*QD],  g_tmpl[(long)BATCHN*QD];
__device__ bf16  g_c2h [(long)BATCHN*QD],  g_c2l [(long)BATCHN*QD];
__device__ bf16  g_w_h[3145728], g_w_l[3145728];
__device__ float g_wf[2*256*256];
__device__ float g_battn[2*256];
__device__ float g_lin[8*256];

__device__ __forceinline__ void split2(float v, bf16& h, bf16& l){
    h = __float2bfloat16(v);
    l = __float2bfloat16(v - __bfloat162float(h));
}
__device__ __forceinline__ unsigned cvsm(const void* p){
    unsigned a;
    asm("{ .reg .u64 t; cvta.to.shared.u64 t, %1; cvt.u32.u64 %0, t; }" : "=r"(a) : "l"(p));
    return a;
}
__device__ __forceinline__ void ldm4(unsigned a, unsigned& r0, unsigned& r1, unsigned& r2, unsigned& r3){
    asm volatile("ldmatrix.sync.aligned.m8n8.x4.shared.b16 {%0,%1,%2,%3}, [%4];"
                 : "=r"(r0),"=r"(r1),"=r"(r2),"=r"(r3) : "r"(a));
}
__device__ __forceinline__ void mmabf(float* c, const unsigned* a, const unsigned* b){
    asm volatile("mma.sync.aligned.m16n8k16.row.col.f32.bf16.bf16.f32 "
                 "{%0,%1,%2,%3},{%4,%5,%6,%7},{%8,%9},{%0,%1,%2,%3};"
                 : "+f"(c[0]),"+f"(c[1]),"+f"(c[2]),"+f"(c[3])
                 : "r"(a[0]),"r"(a[1]),"r"(a[2]),"r"(a[3]),"r"(b[0]),"r"(b[1]));
}

#define BM 128
#define BN 128
#define BKK 64
#define LDT 72                 // bf16 units; 144B rows (16 mod 128 -> conflict-free)
#define ASZ (BM*LDT)           // 9216 bf16 per array
#define STG (4*ASZ)            // Ah,Al,Bh,Bl per stage (bf16 units)
#define SM_TOT (2*STG*2)       // bytes: 2 stages x 73728B = 147456

// LDG phase: fetch next stage into registers (8 x uint4 per thread)
__device__ __forceinline__ void ldg_stage(uint4* p,
    const bf16* __restrict__ Ah, const bf16* __restrict__ Al,
    const bf16* __restrict__ Bh, const bf16* __restrict__ Bl,
    long rowBase, int colBase, int K, int k0, int tid)
{
#pragma unroll
    for(int it=0; it<2; it++){
        int j = tid + (it<<9);
        int r = j>>3, kc0=(j&7)<<3;
        long ga=(rowBase+r)*(long)K + k0 + kc0;
        long gb=((long)(colBase+r))*(long)K + k0 + kc0;
        p[it*4+0]=*(const uint4*)(Ah+ga);
        p[it*4+1]=*(const uint4*)(Al+ga);
        p[it*4+2]=*(const uint4*)(Bh+gb);
        p[it*4+3]=*(const uint4*)(Bl+gb);
    }
}
// STS phase
__device__ __forceinline__ void sts_stage(bf16* st, const uint4* p, int tid){
#pragma unroll
    for(int it=0; it<2; it++){
        int j = tid + (it<<9);
        int r = j>>3, kc0=(j&7)<<3;
        int so=r*LDT+kc0;
        *(uint4*)(st+so)       = p[it*4+0];
        *(uint4*)(st+ASZ+so)   = p[it*4+1];
        *(uint4*)(st+2*ASZ+so) = p[it*4+2];
        *(uint4*)(st+3*ASZ+so) = p[it*4+3];
    }
}

// C[M,N] = epi(A@W + bias). A hi/lo [M][K]; W transposed hi/lo [N][K].
// EPI: 0 none, 1 silu, 2 tanh, 3 fused-combine.
template<int EPI>
__global__ void __launch_bounds__(512,1) gemm_k(
    const bf16* __restrict__ Ah, const bf16* __restrict__ Al,
    const bf16* __restrict__ Bh, const bf16* __restrict__ Bl,
    const float* __restrict__ bias,
    float* __restrict__ C32, bf16* __restrict__ Ch, bf16* __restrict__ Cl,
    const bf16* __restrict__ tmphP, const bf16* __restrict__ tmplP,
    const float* __restrict__ gpP, const float* __restrict__ linP,
    int K, int N)
{
    extern __shared__ bf16 sm[];
    const int tid=threadIdx.x, lane=tid&31, warp=tid>>5;
    const int wm=warp>>2, wn=warp&3;      // 4x4 warp grid, 32x32 warp tiles
    const long rowBase=(long)blockIdx.y*BM;
    const int  colBase=blockIdx.x*BN;

    float acc[2][4][4];
#pragma unroll
    for(int a=0;a<2;a++)
#pragma unroll
    for(int b=0;b<4;b++)
#pragma unroll
    for(int c=0;c<4;c++) acc[a][b][c]=0.f;

    const int nIter=K/BKK;
    uint4 pref[8];
    ldg_stage(pref, Ah,Al,Bh,Bl, rowBase,colBase, K, 0, tid);
    sts_stage(sm, pref, tid);
    __syncthreads();

    for(int i=0;i<nIter;i++){
        // issue next stage's global loads NOW; latency hides under compute below
        if(i+1<nIter)
            ldg_stage(pref, Ah,Al,Bh,Bl, rowBase,colBase, K, (i+1)*BKK, tid);
        bf16* cur = sm + (i&1)*STG;
        bf16* sAh=cur; bf16* sAl=cur+ASZ; bf16* sBh=cur+2*ASZ; bf16* sBl=cur+3*ASZ;
#pragma unroll
        for(int ks=0;ks<4;ks++){
            unsigned aH[2][4], aL[2][4], bH[4][2], bL[4][2];
            const int colo = ks*16 + ((lane>>4)<<3);
#pragma unroll
            for(int mt=0;mt<2;mt++){
                int row=wm*32+mt*16+(lane&15);
                ldm4(cvsm(sAh+row*LDT+colo), aH[mt][0],aH[mt][1],aH[mt][2],aH[mt][3]);
                ldm4(cvsm(sAl+row*LDT+colo), aL[mt][0],aL[mt][1],aL[mt][2],aL[mt][3]);
            }
#pragma unroll
            for(int np=0;np<2;np++){
                int row=wn*32+np*16+(lane&15);
                unsigned t0,t1,t2,t3;
                ldm4(cvsm(sBh+row*LDT+colo), t0,t1,t2,t3);
                bH[2*np][0]=t0; bH[2*np][1]=t2; bH[2*np+1][0]=t1; bH[2*np+1][1]=t3;
                ldm4(cvsm(sBl+row*LDT+colo), t0,t1,t2,t3);
                bL[2*np][0]=t0; bL[2*np][1]=t2; bL[2*np+1][0]=t1; bL[2*np+1][1]=t3;
            }
#pragma unroll
            for(int mt=0;mt<2;mt++)
#pragma unroll
            for(int nt=0;nt<4;nt++){
                mmabf(acc[mt][nt], aH[mt], bH[nt]);
                mmabf(acc[mt][nt], aH[mt], bL[nt]);
                mmabf(acc[mt][nt], aL[mt], bH[nt]);
            }
        }
        if(i+1<nIter){
            sts_stage(sm+((i+1)&1)*STG, pref, tid);
            __syncthreads();
        }
    }

#pragma unroll
    for(int mt=0;mt<2;mt++)
#pragma unroll
    for(int nt=0;nt<4;nt++){
        int n0=colBase+wn*32+nt*8+((lane&3)<<1);
        float b0=0.f,b1=0.f;
        if(EPI!=3 && bias){ b0=bias[n0]; b1=bias[n0+1]; }
        float l0=0,p30=0,p40=0,p50=0,l1=0,p31=0,p41=0,p51=0;
        if(EPI==3){
            l0=linP[n0]; p30=gpP[n0*6+3]; p40=gpP[n0*6+4]; p50=gpP[n0*6+5];
            l1=linP[n0+1]; p31=gpP[(n0+1)*6+3]; p41=gpP[(n0+1)*6+4]; p51=gpP[(n0+1)*6+5];
        }
#pragma unroll
        for(int hh=0;hh<2;hh++){
            long row=rowBase+wm*32+mt*16+(lane>>2)+hh*8;
            long o=row*(long)N+n0;
            float v0=acc[mt][nt][2*hh]+b0, v1=acc[mt][nt][2*hh+1]+b1;
            if(EPI==1){ v0*=1.f/(1.f+__expf(-v0)); v1*=1.f/(1.f+__expf(-v1)); }
            if(EPI==2){ v0=tanhf(v0); v1=tanhf(v1); }
            if(EPI==3){
                __nv_bfloat162 th=*(const __nv_bfloat162*)(tmphP+o);
                __nv_bfloat162 tl=*(const __nv_bfloat162*)(tmplP+o);
                float t0v=__bfloat162float(th.x)+__bfloat162float(tl.x);
                float t1v=__bfloat162float(th.y)+__bfloat162float(tl.y);
                float g0=(l0*t0v + 0.5f*sinf(p30*t0v+p40) + 0.5f*cosf(p50*t0v))*0.25f;
                float g1=(l1*t1v + 0.5f*sinf(p31*t1v+p41) + 0.5f*cosf(p51*t1v))*0.25f;
                v0=(t0v + 0.3f*g0 + 0.2f*v0)*(1.0f/1.5f);
                v1=(t1v + 0.3f*g1 + 0.2f*v1)*(1.0f/1.5f);
            }
            if(C32){ float2 f; f.x=v0; f.y=v1; *(float2*)(C32+o)=f; }
            if(Ch){
                bf16 h0,q0,h1,q1; split2(v0,h0,q0); split2(v1,h1,q1);
                __nv_bfloat162 ph,pl; ph.x=h0; ph.y=h1; pl.x=q0; pl.y=q1;
                *(__nv_bfloat162*)(Ch+o)=ph; *(__nv_bfloat162*)(Cl+o)=pl;
            }
        }
    }
}

__global__ void k_init(const float* __restrict__ x,
                       bf16* __restrict__ ch, bf16* __restrict__ cl){
    long idx=(long)blockIdx.x*256+threadIdx.x;
    float v=x[idx];
    bf16 h,l; split2(v,h,l); ch[idx]=h; cl[idx]=l;
}

__device__ __forceinline__ void split_store(const float* W, bf16* oh, bf16* ol,
                                            int K, int N, int do_tanh, long seg, long idx){
    if(idx>=seg) return;
    int k=(int)(idx/N), n=(int)(idx%N);
    float v=W[idx]; if(do_tanh) v=tanhf(v);
    bf16 h,l; split2(v,h,l);
    oh[(long)n*K+k]=h; ol[(long)n*K+k]=l;
}

__global__ void k_split_big(const float* __restrict__ d0w1, const float* __restrict__ d0w2,
                            const float* __restrict__ d1w1, const float* __restrict__ d1w2,
                            bf16* __restrict__ wh, bf16* __restrict__ wl){
    const long O_D0W1=0, O_D0W2=589824, O_D1W1=1179648, O_D1W2=1572864;
    long idx=(long)blockIdx.x*256+threadIdx.x;
    int y=blockIdx.y;
    if(y<3){        long b=(long)y*196608;
        split_store(d0w1+b, wh+O_D0W1+b, wl+O_D0W1+b, 256,768,0,196608,idx);
    } else if(y<6){ long b=(long)(y-3)*196608;
        split_store(d0w2+b, wh+O_D0W2+b, wl+O_D0W2+b, 768,256,0,196608,idx);
    } else if(y<9){ long b=(long)(y-6)*131072;
        split_store(d1w1+b, wh+O_D1W1+b, wl+O_D1W1+b, 256,512,0,131072,idx);
    } else {        long b=(long)(y-9)*131072;
        split_store(d1w2+b, wh+O_D1W2+b, wl+O_D1W2+b, 512,256,0,131072,idx);
    }
}

__global__ void k_split_small(const float* __restrict__ wf, const float* __restrict__ ent,
                              const float* __restrict__ nw1, const float* __restrict__ nw2,
                              bf16* __restrict__ wh, bf16* __restrict__ wl){
    const long O_ATT=1966080, O_TENT=2097152, O_NW1=2621440, O_NW2=2883584;
    long idx=(long)blockIdx.x*256+threadIdx.x;
    int y=blockIdx.y;
    if(y<2){         long b=(long)y*65536;
        split_store(wf+b,  wh+O_ATT+b,  wl+O_ATT+b,  256,256,0,65536,idx);
    } else if(y<10){ long b=(long)(y-2)*65536;
        split_store(ent+b, wh+O_TENT+b, wl+O_TENT+b, 256,256,1,65536,idx);
    } else if(y<14){ long b=(long)(y-10)*65536;
        split_store(nw1+b, wh+O_NW1+b,  wl+O_NW1+b,  256,256,0,65536,idx);
    } else {         long b=(long)(y-14)*65536;
        split_store(nw2+b, wh+O_NW2+b,  wl+O_NW2+b,  256,256,0,65536,idx);
    }
}

__global__ void k_attn_fuse(const float* __restrict__ wqkv, const float* __restrict__ bqkv,
                            const float* __restrict__ wo, const float* __restrict__ bo,
                            float* __restrict__ wf, float* __restrict__ battn){
    int i=blockIdx.y;
    int idx=blockIdx.x*256+threadIdx.x;
    int k=idx>>8, n=idx&255;
    const float* Wv=wqkv+(long)i*256*768+512;
    const float* Wo=wo+(long)i*256*256;
    float s=0.f;
    for(int j=0;j<256;j++) s+=Wv[(long)k*768+j]*Wo[(long)j*256+n];
    wf[(long)i*65536+idx]=s;
    if(k==0){
        float sb=bo[i*256+n];
        for(int j=0;j<256;j++) sb+=bqkv[(long)i*768+512+j]*Wo[(long)j*256+n];
        battn[i*256+n]=sb;
    }
}

__global__ void k_lin(const float* __restrict__ gp, float* __restrict__ lin){
    int idx=blockIdx.x*256+threadIdx.x;
    const float* p=gp+(long)idx*6;
    lin[idx]=sinf(p[0])+cosf(p[1])+tanhf(p[2]);
}

__global__ void k_ln_gelu(const float* __restrict__ h, const float* __restrict__ w, const float* __restrict__ b,
                          bf16* __restrict__ oh, bf16* __restrict__ ol){
    int row=blockIdx.x*8+(threadIdx.x>>5);
    int lane=threadIdx.x&31;
    const float* hr=h+(long)row*768;
    float v[24]; float s=0.f,s2=0.f;
#pragma unroll
    for(int j=0;j<24;j++){ float x=hr[lane+32*j]; v[j]=x; s+=x; s2+=x*x; }
#pragma unroll
    for(int o=16;o;o>>=1){ s+=__shfl_xor_sync(0xffffffffu,s,o); s2+=__shfl_xor_sync(0xffffffffu,s2,o); }
    float mu=s*(1.f/768.f);
    float var=s2*(1.f/768.f)-mu*mu;
    float inv=rsqrtf(var+1e-5f);
    long base=(long)row*768;
#pragma unroll
    for(int j=0;j<24;j++){
        int q=lane+32*j;
        float y=(v[j]-mu)*inv*w[q]+b[q];
        float g=0.5f*y*(1.f+erff(y*0.70710678118654752f));
        bf16 hh,ll; split2(g,hh,ll);
        oh[base+q]=hh; ol[base+q]=ll;
    }
}

__global__ void k_final(const bf16* __restrict__ c2h, const bf16* __restrict__ c2l,
                        const float* __restrict__ nl,
                        bf16* __restrict__ ch, bf16* __restrict__ cl,
                        float* __restrict__ outp, float alpha){
    int row=blockIdx.x*8+(threadIdx.x>>5);
    int lane=threadIdx.x&31;
    long base=(long)row*QD;
    float v[8]; float ss=0.f;
#pragma unroll
    for(int j=0;j<8;j++){
        int q=lane+32*j;
        float x=__bfloat162float(c2h[base+q])+__bfloat162float(c2l[base+q]);
        if(nl) x+=0.1f*nl[base+q];
        float res=__bfloat162float(ch[base+q])+__bfloat162float(cl[base+q]);
        float y=alpha*x+(1.f-alpha)*res;
        v[j]=y; ss+=y*y;
    }
#pragma unroll
    for(int o=16;o;o>>=1) ss+=__shfl_xor_sync(0xffffffffu,ss,o);
    float inv=1.f/(sqrtf(ss)+1e-8f);
#pragma unroll
    for(int j=0;j<8;j++){
        int q=lane+32*j;
        float y=tanhf(v[j]*inv);
        if(outp) outp[base+q]=y;
        else{ bf16 h,l; split2(y,h,l); ch[base+q]=h; cl[base+q]=l; }
    }
}

static void* symaddr(const void* s){ void* p=nullptr; cudaGetSymbolAddress(&p, s); return p; }

static void gemm(int epi, const bf16* Ah,const bf16* Al,const bf16* Bh,const bf16* Bl,
                 const float* bias, float* C32, bf16* Ch, bf16* Cl,
                 const bf16* tmphP, const bf16* tmplP, const float* gpP, const float* linP,
                 int K,int N){
    dim3 grid(N/128, BATCHN/128);
    if(epi==0)      gemm_k<0><<<grid,512,SM_TOT>>>(Ah,Al,Bh,Bl,bias,C32,Ch,Cl,tmphP,tmplP,gpP,linP,K,N);
    else if(epi==1) gemm_k<1><<<grid,512,SM_TOT>>>(Ah,Al,Bh,Bl,bias,C32,Ch,Cl,tmphP,tmplP,gpP,linP,K,N);
    else if(epi==2) gemm_k<2><<<grid,512,SM_TOT>>>(Ah,Al,Bh,Bl,bias,C32,Ch,Cl,tmphP,tmplP,gpP,linP,K,N);
    else            gemm_k<3><<<grid,512,SM_TOT>>>(Ah,Al,Bh,Bl,bias,C32,Ch,Cl,tmphP,tmplP,gpP,linP,K,N);
}

extern "C" void kernel_launch(void* const* d_in, const int* in_sizes, int n_in,
                              void* d_out, int out_size){
    (void)in_sizes;(void)n_in;(void)out_size;
    cudaFuncSetAttribute(gemm_k<0>, cudaFuncAttributeMaxDynamicSharedMemorySize, SM_TOT);
    cudaFuncSetAttribute(gemm_k<1>, cudaFuncAttributeMaxDynamicSharedMemorySize, SM_TOT);
    cudaFuncSetAttribute(gemm_k<2>, cudaFuncAttributeMaxDynamicSharedMemorySize, SM_TOT);
    cudaFuncSetAttribute(gemm_k<3>, cudaFuncAttributeMaxDynamicSharedMemorySize, SM_TOT);

    const float* x   =(const float*)d_in[0];
    const float* d0w1=(const float*)d_in[1];
    const float* d0b1=(const float*)d_in[2];
    const float* lnw =(const float*)d_in[3];
    const float* lnb =(const float*)d_in[4];
    const float* d0w2=(const float*)d_in[5];
    const float* d0b2=(const float*)d_in[6];
    const float* d1w1=(const float*)d_in[7];
    const float* d1b1=(const float*)d_in[8];
    const float* d1w2=(const float*)d_in[9];
    const float* d1b2=(const float*)d_in[10];
    const float* wqkv=(const float*)d_in[11];
    const float* bqkv=(const float*)d_in[12];
    const float* wo  =(const float*)d_in[13];
    const float* bo  =(const float*)d_in[14];
    const float* gp  =(const float*)d_in[15];
    const float* ent =(const float*)d_in[16];
    const float* nw1 =(const float*)d_in[17];
    const float* nb1 =(const float*)d_in[18];
    const float* nw2 =(const float*)d_in[19];
    const float* nb2 =(const float*)d_in[20];

    float* h32  =(float*)symaddr(g_h32);
    float* nl32 =(float*)symaddr(g_nl32);
    bf16* curh=(bf16*)symaddr(g_curh); bf16* curl=(bf16*)symaddr(g_curl);
    bf16* hh_ =(bf16*)symaddr(g_hh);   bf16* hl_ =(bf16*)symaddr(g_hl);
    bf16* tmph=(bf16*)symaddr(g_tmph); bf16* tmpl=(bf16*)symaddr(g_tmpl);
    bf16* c2h =(bf16*)symaddr(g_c2h);  bf16* c2l =(bf16*)symaddr(g_c2l);
    bf16* wh  =(bf16*)symaddr(g_w_h);  bf16* wl  =(bf16*)symaddr(g_w_l);
    float* wf   =(float*)symaddr(g_wf);
    float* battn=(float*)symaddr(g_battn);
    float* lin  =(float*)symaddr(g_lin);

    const long O_D0W1=0, O_D0W2=589824, O_D1W1=1179648, O_D1W2=1572864;
    const long O_ATT=1966080, O_TENT=2097152, O_NW1=2621440, O_NW2=2883584;

    // launches 1-3 are prep; launch #4 is the first main GEMM (ncu profiles #4)
    k_split_big <<<dim3(768,12),256>>>(d0w1,d0w2,d1w1,d1w2, wh,wl);
    k_init<<<BATCHN*QD/256,256>>>(x, curh, curl);
    k_attn_fuse <<<dim3(256,2),256>>>(wqkv,bqkv,wo,bo,wf,battn);

    for(int li=0;li<8;li++){
        int t=li%3;
        if(t==0){
            int i=li/3;
            gemm(0, curh,curl, wh+O_D0W1+(long)i*196608, wl+O_D0W1+(long)i*196608,
                 d0b1+(long)i*768, h32, nullptr,nullptr, nullptr,nullptr,nullptr,nullptr, 256,768);
            if(li==0){
                k_split_small<<<dim3(256,18),256>>>(wf,ent,nw1,nw2, wh,wl);
                k_lin<<<8,256>>>(gp, lin);
            }
            k_ln_gelu<<<BATCHN/8,256>>>(h32, lnw+(long)i*768, lnb+(long)i*768, hh_, hl_);
            gemm(0, hh_,hl_, wh+O_D0W2+(long)i*196608, wl+O_D0W2+(long)i*196608,
                 d0b2+(long)i*256, nullptr, tmph,tmpl, nullptr,nullptr,nullptr,nullptr, 768,256);
        } else if(t==1){
            int i=(li-1)/3;
            gemm(1, curh,curl, wh+O_D1W1+(long)i*131072, wl+O_D1W1+(long)i*131072,
                 d1b1+(long)i*512, nullptr, hh_,hl_, nullptr,nullptr,nullptr,nullptr, 256,512);
            gemm(0, hh_,hl_, wh+O_D1W2+(long)i*131072, wl+O_D1W2+(long)i*131072,
                 d1b2+(long)i*256, nullptr, tmph,tmpl, nullptr,nullptr,nullptr,nullptr, 512,256);
        } else {
            int i=(li-2)/3;
            gemm(0, curh,curl, wh+O_ATT+(long)i*65536, wl+O_ATT+(long)i*65536,
                 battn+(long)i*256, nullptr, tmph,tmpl, nullptr,nullptr,nullptr,nullptr, 256,256);
        }
        gemm(3, tmph,tmpl, wh+O_TENT+(long)li*65536, wl+O_TENT+(long)li*65536,
             nullptr, nullptr, c2h,c2l, tmph,tmpl, gp+(long)li*256*6, lin+(long)li*256, 256,256);

        const float* nlptr=nullptr;
        if(li&1){
            int j=li/2;
            gemm(2, c2h,c2l, wh+O_NW1+(long)j*65536, wl+O_NW1+(long)j*65536,
                 nb1+(long)j*256, nullptr, hh_,hl_, nullptr,nullptr,nullptr,nullptr, 256,256);
            gemm(0, hh_,hl_, wh+O_NW2+(long)j*65536, wl+O_NW2+(long)j*65536,
                 nb2+(long)j*256, nl32, nullptr,nullptr, nullptr,nullptr,nullptr,nullptr, 256,256);
            nlptr=nl32;
        }
        float alpha=(li<4)?0.8f:0.6f;
        float* outp=(li==7)?(float*)d_out:nullptr;
        k_final<<<BATCHN/8,256>>>(c2h,c2l, nlptr, curh, curl, outp, alpha);
    }
}